// round 6
// baseline (speedup 1.0000x reference)
#include <cuda_runtime.h>

#define NN 10000
#define BB 8
#define TT 20
#define FF 9
#define MAXE 160000
#define BT (BB*TT)   // 160
#define HS 72        // padded Hsm row stride

__device__ float g_X[NN*BT];
__device__ float g_S[NN*BT];
__device__ float g_dinv[NN];
__device__ int   g_cnt[NN];
__device__ int   g_fill[NN];
__device__ int   g_row[NN];
__device__ int2  g_ev[MAXE];
__device__ int   g_is64;

__device__ __forceinline__ unsigned long long pk2(float x){
  unsigned long long r; asm("mov.b64 %0, {%1, %1};" : "=l"(r) : "r"(__float_as_uint(x))); return r;
}
__device__ __forceinline__ unsigned long long f2fma(unsigned long long a, unsigned long long b, unsigned long long c){
  unsigned long long d; asm("fma.rn.f32x2 %0, %1, %2, %3;" : "=l"(d) : "l"(a), "l"(b), "l"(c)); return d;
}
__device__ __forceinline__ float lo32(unsigned long long a){ return __uint_as_float((unsigned)a); }
__device__ __forceinline__ float hi32(unsigned long long a){ return __uint_as_float((unsigned)(a>>32)); }
__device__ __forceinline__ float sigm(float x){ return __fdividef(1.f, 1.f + __expf(-x)); }
__device__ __forceinline__ float tanha(float x){ return 1.f - __fdividef(2.f, __expf(2.f*x) + 1.f); }

// Detect whether edge_index buffer is really int64 (high words all zero) or int32.
__global__ void k_detect(const int* __restrict__ w){
  int i = threadIdx.x;                 // 0..63, inspect words 2i+1 (int64 high halves)
  int v = w[2*i+1];
  unsigned b = __ballot_sync(0xffffffffu, v == 0);
  __shared__ int ok[2];
  if ((i & 31) == 0) ok[i >> 5] = (b == 0xffffffffu);
  __syncthreads();
  if (i == 0) g_is64 = (ok[0] && ok[1]) ? 1 : 0;
}

__global__ void k_init(){
  int i = blockIdx.x*blockDim.x + threadIdx.x;
  if (i < NN){ g_cnt[i]=0; g_fill[i]=0; }
}

// copy x_other into out channels 0..7, transpose x_rec into g_X[n][bt]
__global__ void k_obs(const float* __restrict__ obs, float* __restrict__ out){
  int idx = blockIdx.x*blockDim.x + threadIdx.x;
  if (idx >= BT*NN) return;
  const float* r = obs + (size_t)idx*FF;
  float v[9];
  #pragma unroll
  for (int f=0; f<9; ++f) v[f] = r[f];
  float* o = out + (size_t)idx*72;
  *(float4*)(o)   = make_float4(v[0],v[1],v[2],v[3]);
  *(float4*)(o+4) = make_float4(v[4],v[5],v[6],v[7]);
  int bt = idx / NN, n = idx - bt*NN;
  g_X[n*BT + bt] = v[8];
}

__device__ __forceinline__ int edge_at(const int* w, int is64, int idx){
  return is64 ? w[2*idx] : w[idx];    // little-endian low word
}

__global__ void k_count(const int* __restrict__ w, int E){
  int e = blockIdx.x*blockDim.x + threadIdx.x;
  if (e >= E) return;
  int d = edge_at(w, g_is64, E + e);
  if ((unsigned)d < NN) atomicAdd(&g_cnt[d], 1);
}

__global__ void k_dinv(){
  int n = blockIdx.x*blockDim.x + threadIdx.x;
  if (n < NN) g_dinv[n] = rsqrtf((float)(g_cnt[n] + 1));  // +1 self loop
}

__global__ void k_scan(){
  __shared__ int sums[256];
  int tid = threadIdx.x;
  const int CH = 40;
  int base = tid*CH, s = 0;
  for (int i=0;i<CH;++i){ int ix = base+i; if (ix<NN) s += g_cnt[ix]; }
  sums[tid]=s; __syncthreads();
  for (int off=1; off<256; off<<=1){
    int v = (tid>=off) ? sums[tid-off] : 0;
    __syncthreads();
    sums[tid] += v;
    __syncthreads();
  }
  int run = (tid>0) ? sums[tid-1] : 0;
  for (int i=0;i<CH;++i){ int ix=base+i; if (ix<NN){ g_row[ix]=run; run += g_cnt[ix]; } }
}

__global__ void k_fill(const int* __restrict__ w, int E){
  int e = blockIdx.x*blockDim.x + threadIdx.x;
  if (e >= E) return;
  int is64 = g_is64;
  int sN = edge_at(w, is64, e);
  int d  = edge_at(w, is64, E + e);
  if ((unsigned)sN >= NN || (unsigned)d >= NN) return;
  int pos = g_row[d] + atomicAdd(&g_fill[d], 1);
  g_ev[pos] = make_int2(sN, __float_as_int(g_dinv[sN]*g_dinv[d]));
}

// s[n][bt] = dinv[n]^2 * x[n][bt] + sum_{edges into n} norm * x[src][bt]
__global__ void k_spmm(){
  int w = (blockIdx.x*blockDim.x + threadIdx.x) >> 5;
  int lane = threadIdx.x & 31;
  if (w >= NN*5) return;
  int n = w/5, c = (w - 5*n)*32 + lane;
  float dn = g_dinv[n];
  float acc = dn*dn*g_X[n*BT + c];
  int st = g_row[n], en = st + g_cnt[n];
  for (int i=st; i<en; ++i){
    int2 ev = g_ev[i];
    acc = fmaf(__int_as_float(ev.y), g_X[ev.x*BT + c], acc);
  }
  g_S[n*BT + c] = acc;
}

// 64 (b,n) pairs per CTA of 256 threads. g=tid>>3 -> pairs (base+g, base+32+g);
// q=tid&7 owns H components {4q..4q+3, 32+4q..32+4q+3}. H in registers across
// all 20 steps; weights + per-step H/HR broadcast in SMEM; matvecs on fma.rn.f32x2.
__global__ void __launch_bounds__(256,2) k_gru(
   const float* __restrict__ Wcz, const float* __restrict__ bcz,
   const float* __restrict__ Wlz, const float* __restrict__ blz,
   const float* __restrict__ Wcr, const float* __restrict__ bcr,
   const float* __restrict__ Wlr, const float* __restrict__ blr,
   const float* __restrict__ Wch, const float* __restrict__ bch,
   const float* __restrict__ Wlh, const float* __restrict__ blh,
   float* __restrict__ out)
{
  extern __shared__ __align__(16) float sm[];
  float* Uzr = sm;                 // [64][128]
  float* Uh  = Uzr + 64*128;       // [64][64]
  float* uzr = Uh  + 64*64;        // [128]
  float* czr = uzr + 128;          // [128]
  float* uh2 = czr + 128;          // [64]
  float* ch2 = uh2 + 64;           // [64]
  float* Ssm = ch2 + 64;           // [64][20]
  float* Hsm = Ssm + 64*20;        // [64][HS]
  float* HRsm= Hsm + 64*HS;        // [64][HS]

  int tid = threadIdx.x;
  int q = tid & 7, g = tid >> 3;

  for (int idx = tid; idx < 64*128; idx += 256){
    int k = idx >> 7, j = idx & 127;
    Uzr[idx] = (j < 64) ? Wlz[(64+k)*64 + j] : Wlr[(64+k)*64 + (j-64)];
  }
  for (int idx = tid; idx < 64*64; idx += 256){
    int k = idx >> 6, j = idx & 63;
    Uh[idx] = Wlh[(64+k)*64 + j];
  }
  if (tid < 192){
    if (tid < 128){
      int j = tid & 63;
      const float* W  = (tid<64) ? Wlz : Wlr;
      const float* Wc = (tid<64) ? Wcz : Wcr;
      const float* bc = (tid<64) ? bcz : bcr;
      const float* bl = (tid<64) ? blz : blr;
      float u = 0.f, cc = 0.f;
      for (int k=0;k<64;++k){ float w = W[k*64+j]; u = fmaf(Wc[k], w, u); cc = fmaf(bc[k], w, cc); }
      uzr[tid] = u; czr[tid] = cc + bl[j];
    } else {
      int j = tid - 128;
      float u = 0.f, cc = 0.f;
      for (int k=0;k<64;++k){ float w = Wlh[k*64+j]; u = fmaf(Wch[k], w, u); cc = fmaf(bch[k], w, cc); }
      uh2[j] = u; ch2[j] = cc + blh[j];
    }
  }
  int pbase = blockIdx.x*64;
  for (int idx = tid; idx < 64*20; idx += 256){
    int r = idx/20, t = idx - 20*r;
    int p = pbase + r; int b = p/NN, n = p - b*NN;
    Ssm[idx] = g_S[n*BT + b*TT + t];
  }
  for (int idx = tid; idx < 64*HS; idx += 256) Hsm[idx] = 0.f;
  __syncthreads();

  int pA = pbase + g,      pB = pbase + 32 + g;
  int bA = pA/NN, nA = pA - bA*NN;
  int bB = pB/NN, nB = pB - bB*NN;
  int rA = g, rB = g + 32;
  float* outA = out + ((size_t)(bA*TT)*NN + nA)*72 + 8 + 4*q;
  float* outB = out + ((size_t)(bB*TT)*NN + nB)*72 + 8 + 4*q;

  float hA[8], hB[8], zA[8], zB[8];
  #pragma unroll
  for (int i=0;i<8;++i){ hA[i]=0.f; hB[i]=0.f; }

  for (int t=0; t<TT; ++t){
    float sA = Ssm[rA*20+t], sB = Ssm[rB*20+t];

    // ---- pre_{Z|R} = H . Uzr ----
    unsigned long long aA[8], aB[8];
    #pragma unroll
    for (int i=0;i<8;++i){ aA[i]=0ull; aB[i]=0ull; }
    const float* UzrQ = Uzr + 4*q;
    #pragma unroll 4
    for (int k=0;k<64;++k){
      unsigned long long hhA = pk2(Hsm[rA*HS+k]);
      unsigned long long hhB = pk2(Hsm[rB*HS+k]);
      const float* urow = UzrQ + k*128;
      #pragma unroll
      for (int m=0;m<4;++m){
        float4 u = *(const float4*)(urow + m*32);
        unsigned long long ux, uy;
        asm("mov.b64 %0, {%1, %2};" : "=l"(ux) : "r"(__float_as_uint(u.x)), "r"(__float_as_uint(u.y)));
        asm("mov.b64 %0, {%1, %2};" : "=l"(uy) : "r"(__float_as_uint(u.z)), "r"(__float_as_uint(u.w)));
        aA[2*m]   = f2fma(ux, hhA, aA[2*m]);
        aA[2*m+1] = f2fma(uy, hhA, aA[2*m+1]);
        aB[2*m]   = f2fma(ux, hhB, aB[2*m]);
        aB[2*m+1] = f2fma(uy, hhB, aB[2*m+1]);
      }
    }
    // Z gates (cols 0..63)
    #pragma unroll
    for (int m=0;m<2;++m){
      #pragma unroll
      for (int i=0;i<4;++i){
        int col = m*32 + 4*q + i;
        float accA = (i&1) ? hi32(aA[2*m+(i>>1)]) : lo32(aA[2*m+(i>>1)]);
        float accB = (i&1) ? hi32(aB[2*m+(i>>1)]) : lo32(aB[2*m+(i>>1)]);
        float uc = uzr[col], cc = czr[col];
        zA[4*m+i] = sigm(fmaf(sA, uc, accA + cc));
        zB[4*m+i] = sigm(fmaf(sB, uc, accB + cc));
      }
    }
    // R gates (cols 64..127) -> HR = H*R staged to SMEM
    #pragma unroll
    for (int m=2;m<4;++m){
      float4 hrA, hrB;
      #pragma unroll
      for (int i=0;i<4;++i){
        int col = m*32 + 4*q + i;
        float accA = (i&1) ? hi32(aA[2*m+(i>>1)]) : lo32(aA[2*m+(i>>1)]);
        float accB = (i&1) ? hi32(aB[2*m+(i>>1)]) : lo32(aB[2*m+(i>>1)]);
        float uc = uzr[col], cc = czr[col];
        float rgA = sigm(fmaf(sA, uc, accA + cc));
        float rgB = sigm(fmaf(sB, uc, accB + cc));
        ((float*)&hrA)[i] = hA[4*(m-2)+i] * rgA;
        ((float*)&hrB)[i] = hB[4*(m-2)+i] * rgB;
      }
      *(float4*)(HRsm + rA*HS + (m-2)*32 + 4*q) = hrA;
      *(float4*)(HRsm + rB*HS + (m-2)*32 + 4*q) = hrB;
    }
    __syncthreads();

    // ---- pre_h = (H*R) . Uh ----
    unsigned long long cA[4], cB[4];
    #pragma unroll
    for (int i=0;i<4;++i){ cA[i]=0ull; cB[i]=0ull; }
    const float* UhQ = Uh + 4*q;
    #pragma unroll 4
    for (int k=0;k<64;++k){
      unsigned long long hhA = pk2(HRsm[rA*HS+k]);
      unsigned long long hhB = pk2(HRsm[rB*HS+k]);
      const float* urow = UhQ + k*64;
      float4 u0 = *(const float4*)(urow);
      float4 u1 = *(const float4*)(urow + 32);
      unsigned long long u0x, u0y, u1x, u1y;
      asm("mov.b64 %0, {%1, %2};" : "=l"(u0x) : "r"(__float_as_uint(u0.x)), "r"(__float_as_uint(u0.y)));
      asm("mov.b64 %0, {%1, %2};" : "=l"(u0y) : "r"(__float_as_uint(u0.z)), "r"(__float_as_uint(u0.w)));
      asm("mov.b64 %0, {%1, %2};" : "=l"(u1x) : "r"(__float_as_uint(u1.x)), "r"(__float_as_uint(u1.y)));
      asm("mov.b64 %0, {%1, %2};" : "=l"(u1y) : "r"(__float_as_uint(u1.z)), "r"(__float_as_uint(u1.w)));
      cA[0] = f2fma(u0x, hhA, cA[0]);
      cA[1] = f2fma(u0y, hhA, cA[1]);
      cA[2] = f2fma(u1x, hhA, cA[2]);
      cA[3] = f2fma(u1y, hhA, cA[3]);
      cB[0] = f2fma(u0x, hhB, cB[0]);
      cB[1] = f2fma(u0y, hhB, cB[1]);
      cB[2] = f2fma(u1x, hhB, cB[2]);
      cB[3] = f2fma(u1y, hhB, cB[3]);
    }

    // ---- Htil, Hn; write out + Hsm ----
    #pragma unroll
    for (int i=0;i<8;++i){
      int col = (i<4) ? (4*q + i) : (32 + 4*q + (i-4));
      int ai = (i<4) ? (i>>1) : (2 + ((i-4)>>1));
      float accA = (i&1) ? hi32(cA[ai]) : lo32(cA[ai]);
      float accB = (i&1) ? hi32(cB[ai]) : lo32(cB[ai]);
      float uc = uh2[col], cc = ch2[col];
      float htA = tanha(fmaf(sA, uc, accA + cc));
      float htB = tanha(fmaf(sB, uc, accB + cc));
      hA[i] = zA[i]*hA[i] + (1.f - zA[i])*htA;
      hB[i] = zB[i]*hB[i] + (1.f - zB[i])*htB;
    }
    *(float4*)(Hsm + rA*HS + 4*q)      = make_float4(hA[0],hA[1],hA[2],hA[3]);
    *(float4*)(Hsm + rA*HS + 32 + 4*q) = make_float4(hA[4],hA[5],hA[6],hA[7]);
    *(float4*)(Hsm + rB*HS + 4*q)      = make_float4(hB[0],hB[1],hB[2],hB[3]);
    *(float4*)(Hsm + rB*HS + 32 + 4*q) = make_float4(hB[4],hB[5],hB[6],hB[7]);
    *(float4*)(outA)      = make_float4(hA[0],hA[1],hA[2],hA[3]);
    *(float4*)(outA + 32) = make_float4(hA[4],hA[5],hA[6],hA[7]);
    *(float4*)(outB)      = make_float4(hB[0],hB[1],hB[2],hB[3]);
    *(float4*)(outB + 32) = make_float4(hB[4],hB[5],hB[6],hB[7]);
    outA += (size_t)NN*72;
    outB += (size_t)NN*72;
    __syncthreads();
  }
}

extern "C" void kernel_launch(void* const* d_in, const int* in_sizes, int n_in,
                              void* d_out, int out_size) {
  const float* obs = (const float*)d_in[0];
  const int* ei32 = (const int*)d_in[1];   // edge_index viewed as int32 words
  int E = in_sizes[1] / 2;
  if (E > MAXE) E = MAXE;
  float* out = (float*)d_out;

  const int SMB = (64*128 + 64*64 + 128+128+64+64 + 64*20 + 64*HS + 64*HS)*4;
  cudaFuncSetAttribute(k_gru, cudaFuncAttributeMaxDynamicSharedMemorySize, SMB);

  k_detect<<<1, 64>>>(ei32);
  k_init<<<(NN+255)/256, 256>>>();
  k_obs<<<(BT*NN+255)/256, 256>>>(obs, out);
  k_count<<<(E+255)/256, 256>>>(ei32, E);
  k_dinv<<<(NN+255)/256, 256>>>();
  k_scan<<<1, 256>>>();
  k_fill<<<(E+255)/256, 256>>>(ei32, E);
  k_spmm<<<(NN*5*32+255)/256, 256>>>();
  k_gru<<<(BB*NN)/64, 256, SMB>>>(
    (const float*)d_in[2], (const float*)d_in[3], (const float*)d_in[4], (const float*)d_in[5],
    (const float*)d_in[6], (const float*)d_in[7], (const float*)d_in[8], (const float*)d_in[9],
    (const float*)d_in[10], (const float*)d_in[11], (const float*)d_in[12], (const float*)d_in[13],
    out);
}

// round 7
// speedup vs baseline: 1.0309x; 1.0309x over previous
#include <cuda_runtime.h>

#define NN 10000
#define BB 8
#define TT 20
#define FF 9
#define MAXE 160000
#define BT (BB*TT)   // 160
#define HS 72        // padded Hsm row stride

__device__ float g_X[NN*BT];
__device__ float g_S[NN*BT];
__device__ float g_dinv[NN];
__device__ int   g_cnt[NN];
__device__ int   g_fill[NN];
__device__ int   g_row[NN];
__device__ int2  g_ev[MAXE];
__device__ int   g_is64;

__device__ __forceinline__ unsigned long long pk2(float x){
  unsigned long long r; asm("mov.b64 %0, {%1, %1};" : "=l"(r) : "r"(__float_as_uint(x))); return r;
}
__device__ __forceinline__ unsigned long long f2fma(unsigned long long a, unsigned long long b, unsigned long long c){
  unsigned long long d; asm("fma.rn.f32x2 %0, %1, %2, %3;" : "=l"(d) : "l"(a), "l"(b), "l"(c)); return d;
}
__device__ __forceinline__ float lo32(unsigned long long a){ return __uint_as_float((unsigned)a); }
__device__ __forceinline__ float hi32(unsigned long long a){ return __uint_as_float((unsigned)(a>>32)); }
__device__ __forceinline__ float sigm(float x){ return __fdividef(1.f, 1.f + __expf(-x)); }
__device__ __forceinline__ float tanha(float x){ return 1.f - __fdividef(2.f, __expf(2.f*x) + 1.f); }

// Detect whether edge_index buffer is really int64 (high words all zero) or int32.
__global__ void k_detect(const int* __restrict__ w){
  int i = threadIdx.x;
  int v = w[2*i+1];
  unsigned b = __ballot_sync(0xffffffffu, v == 0);
  __shared__ int ok[2];
  if ((i & 31) == 0) ok[i >> 5] = (b == 0xffffffffu);
  __syncthreads();
  if (i == 0) g_is64 = (ok[0] && ok[1]) ? 1 : 0;
}

__global__ void k_init(){
  int i = blockIdx.x*blockDim.x + threadIdx.x;
  if (i < NN){ g_cnt[i]=0; g_fill[i]=0; }
}

__global__ void k_obs(const float* __restrict__ obs, float* __restrict__ out){
  int idx = blockIdx.x*blockDim.x + threadIdx.x;
  if (idx >= BT*NN) return;
  const float* r = obs + (size_t)idx*FF;
  float v[9];
  #pragma unroll
  for (int f=0; f<9; ++f) v[f] = r[f];
  float* o = out + (size_t)idx*72;
  *(float4*)(o)   = make_float4(v[0],v[1],v[2],v[3]);
  *(float4*)(o+4) = make_float4(v[4],v[5],v[6],v[7]);
  int bt = idx / NN, n = idx - bt*NN;
  g_X[n*BT + bt] = v[8];
}

__device__ __forceinline__ int edge_at(const int* w, int is64, int idx){
  return is64 ? w[2*idx] : w[idx];
}

__global__ void k_count(const int* __restrict__ w, int E){
  int e = blockIdx.x*blockDim.x + threadIdx.x;
  if (e >= E) return;
  int d = edge_at(w, g_is64, E + e);
  if ((unsigned)d < NN) atomicAdd(&g_cnt[d], 1);
}

__global__ void k_dinv(){
  int n = blockIdx.x*blockDim.x + threadIdx.x;
  if (n < NN) g_dinv[n] = rsqrtf((float)(g_cnt[n] + 1));
}

__global__ void k_scan(){
  __shared__ int sums[256];
  int tid = threadIdx.x;
  const int CH = 40;
  int base = tid*CH, s = 0;
  for (int i=0;i<CH;++i){ int ix = base+i; if (ix<NN) s += g_cnt[ix]; }
  sums[tid]=s; __syncthreads();
  for (int off=1; off<256; off<<=1){
    int v = (tid>=off) ? sums[tid-off] : 0;
    __syncthreads();
    sums[tid] += v;
    __syncthreads();
  }
  int run = (tid>0) ? sums[tid-1] : 0;
  for (int i=0;i<CH;++i){ int ix=base+i; if (ix<NN){ g_row[ix]=run; run += g_cnt[ix]; } }
}

__global__ void k_fill(const int* __restrict__ w, int E){
  int e = blockIdx.x*blockDim.x + threadIdx.x;
  if (e >= E) return;
  int is64 = g_is64;
  int sN = edge_at(w, is64, e);
  int d  = edge_at(w, is64, E + e);
  if ((unsigned)sN >= NN || (unsigned)d >= NN) return;
  int pos = g_row[d] + atomicAdd(&g_fill[d], 1);
  g_ev[pos] = make_int2(sN, __float_as_int(g_dinv[sN]*g_dinv[d]));
}

__global__ void k_spmm(){
  int w = (blockIdx.x*blockDim.x + threadIdx.x) >> 5;
  int lane = threadIdx.x & 31;
  if (w >= NN*5) return;
  int n = w/5, c = (w - 5*n)*32 + lane;
  float dn = g_dinv[n];
  float acc = dn*dn*g_X[n*BT + c];
  int st = g_row[n], en = st + g_cnt[n];
  for (int i=st; i<en; ++i){
    int2 ev = g_ev[i];
    acc = fmaf(__int_as_float(ev.y), g_X[ev.x*BT + c], acc);
  }
  g_S[n*BT + c] = acc;
}

// 64 (b,n) pairs per CTA of 256 threads. Warp w owns g in {4w..4w+3}; rows
// rA=g / rB=32+g of Hsm/HRsm are warp-private -> only __syncwarp in the loop.
// Weights loaded as ulonglong2 straight into f2fma operands (no packing MOVs).
__global__ void __launch_bounds__(256,2) k_gru(
   const float* __restrict__ Wcz, const float* __restrict__ bcz,
   const float* __restrict__ Wlz, const float* __restrict__ blz,
   const float* __restrict__ Wcr, const float* __restrict__ bcr,
   const float* __restrict__ Wlr, const float* __restrict__ blr,
   const float* __restrict__ Wch, const float* __restrict__ bch,
   const float* __restrict__ Wlh, const float* __restrict__ blh,
   float* __restrict__ out)
{
  extern __shared__ __align__(16) float sm[];
  float* Uzr = sm;                 // [64][128]
  float* Uh  = Uzr + 64*128;       // [64][64]
  float* uzr = Uh  + 64*64;        // [128]
  float* czr = uzr + 128;          // [128]
  float* uh2 = czr + 128;          // [64]
  float* ch2 = uh2 + 64;           // [64]
  float* Ssm = ch2 + 64;           // [64][20]
  float* Hsm = Ssm + 64*20;        // [64][HS]
  float* HRsm= Hsm + 64*HS;        // [64][HS]

  int tid = threadIdx.x;
  int q = tid & 7, g = tid >> 3;

  for (int idx = tid; idx < 64*128; idx += 256){
    int k = idx >> 7, j = idx & 127;
    Uzr[idx] = (j < 64) ? Wlz[(64+k)*64 + j] : Wlr[(64+k)*64 + (j-64)];
  }
  for (int idx = tid; idx < 64*64; idx += 256){
    int k = idx >> 6, j = idx & 63;
    Uh[idx] = Wlh[(64+k)*64 + j];
  }
  if (tid < 192){
    if (tid < 128){
      int j = tid & 63;
      const float* W  = (tid<64) ? Wlz : Wlr;
      const float* Wc = (tid<64) ? Wcz : Wcr;
      const float* bc = (tid<64) ? bcz : bcr;
      const float* bl = (tid<64) ? blz : blr;
      float u = 0.f, cc = 0.f;
      for (int k=0;k<64;++k){ float w = W[k*64+j]; u = fmaf(Wc[k], w, u); cc = fmaf(bc[k], w, cc); }
      uzr[tid] = u; czr[tid] = cc + bl[j];
    } else {
      int j = tid - 128;
      float u = 0.f, cc = 0.f;
      for (int k=0;k<64;++k){ float w = Wlh[k*64+j]; u = fmaf(Wch[k], w, u); cc = fmaf(bch[k], w, cc); }
      uh2[j] = u; ch2[j] = cc + blh[j];
    }
  }
  int pbase = blockIdx.x*64;
  for (int idx = tid; idx < 64*20; idx += 256){
    int r = idx/20, t = idx - 20*r;
    int p = pbase + r; int b = p/NN, n = p - b*NN;
    Ssm[idx] = g_S[n*BT + b*TT + t];
  }
  for (int idx = tid; idx < 64*HS; idx += 256) Hsm[idx] = 0.f;
  __syncthreads();

  int pA = pbase + g,      pB = pbase + 32 + g;
  int bA = pA/NN, nA = pA - bA*NN;
  int bB = pB/NN, nB = pB - bB*NN;
  int rA = g, rB = g + 32;
  float* outA = out + ((size_t)(bA*TT)*NN + nA)*72 + 8 + 4*q;
  float* outB = out + ((size_t)(bB*TT)*NN + nB)*72 + 8 + 4*q;

  float hA[8], hB[8], zA[8], zB[8];
  #pragma unroll
  for (int i=0;i<8;++i){ hA[i]=0.f; hB[i]=0.f; }

  for (int t=0; t<TT; ++t){
    float sA = Ssm[rA*20+t], sB = Ssm[rB*20+t];

    // ---- pre_{Z|R} = H . Uzr ----
    unsigned long long aA[8], aB[8];
    #pragma unroll
    for (int i=0;i<8;++i){ aA[i]=0ull; aB[i]=0ull; }
    const float* UzrQ = Uzr + 4*q;
    #pragma unroll 4
    for (int k=0;k<64;++k){
      unsigned long long hhA = pk2(Hsm[rA*HS+k]);
      unsigned long long hhB = pk2(Hsm[rB*HS+k]);
      const float* urow = UzrQ + k*128;
      #pragma unroll
      for (int m=0;m<4;++m){
        ulonglong2 uu = *(const ulonglong2*)(urow + m*32);
        aA[2*m]   = f2fma(uu.x, hhA, aA[2*m]);
        aA[2*m+1] = f2fma(uu.y, hhA, aA[2*m+1]);
        aB[2*m]   = f2fma(uu.x, hhB, aB[2*m]);
        aB[2*m+1] = f2fma(uu.y, hhB, aB[2*m+1]);
      }
    }
    // Z gates (cols 0..63)
    #pragma unroll
    for (int m=0;m<2;++m){
      #pragma unroll
      for (int i=0;i<4;++i){
        int col = m*32 + 4*q + i;
        float accA = (i&1) ? hi32(aA[2*m+(i>>1)]) : lo32(aA[2*m+(i>>1)]);
        float accB = (i&1) ? hi32(aB[2*m+(i>>1)]) : lo32(aB[2*m+(i>>1)]);
        float uc = uzr[col], cc = czr[col];
        zA[4*m+i] = sigm(fmaf(sA, uc, accA + cc));
        zB[4*m+i] = sigm(fmaf(sB, uc, accB + cc));
      }
    }
    // R gates (cols 64..127) -> HR = H*R staged to warp-private SMEM rows
    #pragma unroll
    for (int m=2;m<4;++m){
      float4 hrA, hrB;
      #pragma unroll
      for (int i=0;i<4;++i){
        int col = m*32 + 4*q + i;
        float accA = (i&1) ? hi32(aA[2*m+(i>>1)]) : lo32(aA[2*m+(i>>1)]);
        float accB = (i&1) ? hi32(aB[2*m+(i>>1)]) : lo32(aB[2*m+(i>>1)]);
        float uc = uzr[col], cc = czr[col];
        float rgA = sigm(fmaf(sA, uc, accA + cc));
        float rgB = sigm(fmaf(sB, uc, accB + cc));
        ((float*)&hrA)[i] = hA[4*(m-2)+i] * rgA;
        ((float*)&hrB)[i] = hB[4*(m-2)+i] * rgB;
      }
      *(float4*)(HRsm + rA*HS + (m-2)*32 + 4*q) = hrA;
      *(float4*)(HRsm + rB*HS + (m-2)*32 + 4*q) = hrB;
    }
    __syncwarp();

    // ---- pre_h = (H*R) . Uh ----
    unsigned long long cA[4], cB[4];
    #pragma unroll
    for (int i=0;i<4;++i){ cA[i]=0ull; cB[i]=0ull; }
    const float* UhQ = Uh + 4*q;
    #pragma unroll 4
    for (int k=0;k<64;++k){
      unsigned long long hhA = pk2(HRsm[rA*HS+k]);
      unsigned long long hhB = pk2(HRsm[rB*HS+k]);
      const float* urow = UhQ + k*64;
      ulonglong2 u0 = *(const ulonglong2*)(urow);
      ulonglong2 u1 = *(const ulonglong2*)(urow + 32);
      cA[0] = f2fma(u0.x, hhA, cA[0]);
      cA[1] = f2fma(u0.y, hhA, cA[1]);
      cA[2] = f2fma(u1.x, hhA, cA[2]);
      cA[3] = f2fma(u1.y, hhA, cA[3]);
      cB[0] = f2fma(u0.x, hhB, cB[0]);
      cB[1] = f2fma(u0.y, hhB, cB[1]);
      cB[2] = f2fma(u1.x, hhB, cB[2]);
      cB[3] = f2fma(u1.y, hhB, cB[3]);
    }

    // ---- Htil, Hn; write out + Hsm ----
    #pragma unroll
    for (int i=0;i<8;++i){
      int col = (i<4) ? (4*q + i) : (32 + 4*q + (i-4));
      int ai = (i<4) ? (i>>1) : (2 + ((i-4)>>1));
      float accA = (i&1) ? hi32(cA[ai]) : lo32(cA[ai]);
      float accB = (i&1) ? hi32(cB[ai]) : lo32(cB[ai]);
      float uc = uh2[col], cc = ch2[col];
      float htA = tanha(fmaf(sA, uc, accA + cc));
      float htB = tanha(fmaf(sB, uc, accB + cc));
      hA[i] = zA[i]*hA[i] + (1.f - zA[i])*htA;
      hB[i] = zB[i]*hB[i] + (1.f - zB[i])*htB;
    }
    *(float4*)(Hsm + rA*HS + 4*q)      = make_float4(hA[0],hA[1],hA[2],hA[3]);
    *(float4*)(Hsm + rA*HS + 32 + 4*q) = make_float4(hA[4],hA[5],hA[6],hA[7]);
    *(float4*)(Hsm + rB*HS + 4*q)      = make_float4(hB[0],hB[1],hB[2],hB[3]);
    *(float4*)(Hsm + rB*HS + 32 + 4*q) = make_float4(hB[4],hB[5],hB[6],hB[7]);
    *(float4*)(outA)      = make_float4(hA[0],hA[1],hA[2],hA[3]);
    *(float4*)(outA + 32) = make_float4(hA[4],hA[5],hA[6],hA[7]);
    *(float4*)(outB)      = make_float4(hB[0],hB[1],hB[2],hB[3]);
    *(float4*)(outB + 32) = make_float4(hB[4],hB[5],hB[6],hB[7]);
    outA += (size_t)NN*72;
    outB += (size_t)NN*72;
    __syncwarp();
  }
}

extern "C" void kernel_launch(void* const* d_in, const int* in_sizes, int n_in,
                              void* d_out, int out_size) {
  const float* obs = (const float*)d_in[0];
  const int* ei32 = (const int*)d_in[1];
  int E = in_sizes[1] / 2;
  if (E > MAXE) E = MAXE;
  float* out = (float*)d_out;

  const int SMB = (64*128 + 64*64 + 128+128+64+64 + 64*20 + 64*HS + 64*HS)*4;
  cudaFuncSetAttribute(k_gru, cudaFuncAttributeMaxDynamicSharedMemorySize, SMB);

  k_detect<<<1, 64>>>(ei32);
  k_init<<<(NN+255)/256, 256>>>();
  k_obs<<<(BT*NN+255)/256, 256>>>(obs, out);
  k_count<<<(E+255)/256, 256>>>(ei32, E);
  k_dinv<<<(NN+255)/256, 256>>>();
  k_scan<<<1, 256>>>();
  k_fill<<<(E+255)/256, 256>>>(ei32, E);
  k_spmm<<<(NN*5*32+255)/256, 256>>>();
  k_gru<<<(BB*NN)/64, 256, SMB>>>(
    (const float*)d_in[2], (const float*)d_in[3], (const float*)d_in[4], (const float*)d_in[5],
    (const float*)d_in[6], (const float*)d_in[7], (const float*)d_in[8], (const float*)d_in[9],
    (const float*)d_in[10], (const float*)d_in[11], (const float*)d_in[12], (const float*)d_in[13],
    out);
}

// round 9
// speedup vs baseline: 1.0442x; 1.0129x over previous
#include <cuda_runtime.h>

#define NN 10000
#define BB 8
#define TT 20
#define FF 9
#define MAXE 160000
#define BT (BB*TT)   // 160
#define HS 72        // padded Hsm row stride

__device__ float g_X[NN*BT];
__device__ float g_S[NN*BT];
__device__ float g_dinv[NN];
__device__ int   g_cnt[NN];
__device__ int   g_fill[NN];
__device__ int   g_row[NN];
__device__ int2  g_ev[MAXE];
__device__ int   g_is64;

__device__ __forceinline__ unsigned long long pk2(float x){
  unsigned long long r; asm("mov.b64 %0, {%1, %1};" : "=l"(r) : "r"(__float_as_uint(x))); return r;
}
__device__ __forceinline__ unsigned long long f2fma(unsigned long long a, unsigned long long b, unsigned long long c){
  unsigned long long d; asm("fma.rn.f32x2 %0, %1, %2, %3;" : "=l"(d) : "l"(a), "l"(b), "l"(c)); return d;
}
__device__ __forceinline__ float lo32(unsigned long long a){ return __uint_as_float((unsigned)a); }
__device__ __forceinline__ float hi32(unsigned long long a){ return __uint_as_float((unsigned)(a>>32)); }
__device__ __forceinline__ float sigm(float x){ return __fdividef(1.f, 1.f + __expf(-x)); }
__device__ __forceinline__ float tanha(float x){ return 1.f - __fdividef(2.f, __expf(2.f*x) + 1.f); }

// ---------------- prep kernels (unchanged from passing R7) ----------------
__global__ void k_detect(const int* __restrict__ w){
  int i = threadIdx.x;
  int v = w[2*i+1];
  unsigned b = __ballot_sync(0xffffffffu, v == 0);
  __shared__ int ok[2];
  if ((i & 31) == 0) ok[i >> 5] = (b == 0xffffffffu);
  __syncthreads();
  if (i == 0) g_is64 = (ok[0] && ok[1]) ? 1 : 0;
}
__global__ void k_init(){
  int i = blockIdx.x*blockDim.x + threadIdx.x;
  if (i < NN){ g_cnt[i]=0; g_fill[i]=0; }
}
__global__ void k_obs(const float* __restrict__ obs, float* __restrict__ out){
  int idx = blockIdx.x*blockDim.x + threadIdx.x;
  if (idx >= BT*NN) return;
  const float* r = obs + (size_t)idx*FF;
  float v[9];
  #pragma unroll
  for (int f=0; f<9; ++f) v[f] = r[f];
  float* o = out + (size_t)idx*72;
  *(float4*)(o)   = make_float4(v[0],v[1],v[2],v[3]);
  *(float4*)(o+4) = make_float4(v[4],v[5],v[6],v[7]);
  int bt = idx / NN, n = idx - bt*NN;
  g_X[n*BT + bt] = v[8];
}
__device__ __forceinline__ int edge_at(const int* w, int is64, int idx){
  return is64 ? w[2*idx] : w[idx];
}
__global__ void k_count(const int* __restrict__ w, int E){
  int e = blockIdx.x*blockDim.x + threadIdx.x;
  if (e >= E) return;
  int d = edge_at(w, g_is64, E + e);
  if ((unsigned)d < NN) atomicAdd(&g_cnt[d], 1);
}
__global__ void k_dinv(){
  int n = blockIdx.x*blockDim.x + threadIdx.x;
  if (n < NN) g_dinv[n] = rsqrtf((float)(g_cnt[n] + 1));
}
__global__ void k_scan(){
  __shared__ int sums[256];
  int tid = threadIdx.x;
  const int CH = 40;
  int base = tid*CH, s = 0;
  for (int i=0;i<CH;++i){ int ix = base+i; if (ix<NN) s += g_cnt[ix]; }
  sums[tid]=s; __syncthreads();
  for (int off=1; off<256; off<<=1){
    int v = (tid>=off) ? sums[tid-off] : 0;
    __syncthreads();
    sums[tid] += v;
    __syncthreads();
  }
  int run = (tid>0) ? sums[tid-1] : 0;
  for (int i=0;i<CH;++i){ int ix=base+i; if (ix<NN){ g_row[ix]=run; run += g_cnt[ix]; } }
}
__global__ void k_fill(const int* __restrict__ w, int E){
  int e = blockIdx.x*blockDim.x + threadIdx.x;
  if (e >= E) return;
  int is64 = g_is64;
  int sN = edge_at(w, is64, e);
  int d  = edge_at(w, is64, E + e);
  if ((unsigned)sN >= NN || (unsigned)d >= NN) return;
  int pos = g_row[d] + atomicAdd(&g_fill[d], 1);
  g_ev[pos] = make_int2(sN, __float_as_int(g_dinv[sN]*g_dinv[d]));
}
__global__ void k_spmm(){
  int w = (blockIdx.x*blockDim.x + threadIdx.x) >> 5;
  int lane = threadIdx.x & 31;
  if (w >= NN*5) return;
  int n = w/5, c = (w - 5*n)*32 + lane;
  float dn = g_dinv[n];
  float acc = dn*dn*g_X[n*BT + c];
  int st = g_row[n], en = st + g_cnt[n];
  for (int i=st; i<en; ++i){
    int2 ev = g_ev[i];
    acc = fmaf(__int_as_float(ev.y), g_X[ev.x*BT + c], acc);
  }
  g_S[n*BT + c] = acc;
}

// 8-column (per pair) half-matvec on fma.rn.f32x2.
// acc layout: aX[0]=(c0,c1) aX[1]=(c2,c3) of cols base+4q.., aX[2..3] = cols base+32+4q..
__device__ __forceinline__ void matvec8(const float* __restrict__ Wq, int rs,
                                        const float* __restrict__ HA,
                                        const float* __restrict__ HB,
                                        unsigned long long* aA, unsigned long long* aB){
  #pragma unroll
  for (int i=0;i<4;++i){ aA[i]=0ull; aB[i]=0ull; }
  #pragma unroll 4
  for (int k=0;k<64;++k){
    unsigned long long hhA = pk2(HA[k]);
    unsigned long long hhB = pk2(HB[k]);
    const float* urow = Wq + k*rs;
    ulonglong2 u0 = *(const ulonglong2*)(urow);
    ulonglong2 u1 = *(const ulonglong2*)(urow + 32);
    aA[0] = f2fma(u0.x, hhA, aA[0]);
    aA[1] = f2fma(u0.y, hhA, aA[1]);
    aA[2] = f2fma(u1.x, hhA, aA[2]);
    aA[3] = f2fma(u1.y, hhA, aA[3]);
    aB[0] = f2fma(u0.x, hhB, aB[0]);
    aB[1] = f2fma(u0.y, hhB, aB[1]);
    aB[2] = f2fma(u1.x, hhB, aB[2]);
    aB[3] = f2fma(u1.y, hhB, aB[3]);
  }
}

// 64 (b,n) pairs per CTA of 256 threads, 3 CTAs/SM. Warp w owns g in {4w..4w+3};
// Hsm rows rA=g / rB=32+g are warp-private. HR reuses Hsm storage (H is in regs).
__global__ void __launch_bounds__(256,3) k_gru(
   const float* __restrict__ Wcz, const float* __restrict__ bcz,
   const float* __restrict__ Wlz, const float* __restrict__ blz,
   const float* __restrict__ Wcr, const float* __restrict__ bcr,
   const float* __restrict__ Wlr, const float* __restrict__ blr,
   const float* __restrict__ Wch, const float* __restrict__ bch,
   const float* __restrict__ Wlh, const float* __restrict__ blh,
   float* __restrict__ out)
{
  extern __shared__ __align__(16) float sm[];
  float* Uzr = sm;                 // [64][128]
  float* Uh  = Uzr + 64*128;       // [64][64]
  float* uzr = Uh  + 64*64;        // [128]
  float* czr = uzr + 128;          // [128]
  float* uh2 = czr + 128;          // [64]
  float* ch2 = uh2 + 64;           // [64]
  float* Ssm = ch2 + 64;           // [64][20]
  float* Hsm = Ssm + 64*20;        // [64][HS]  (also holds HR transiently)

  int tid = threadIdx.x;
  int q = tid & 7, g = tid >> 3;

  for (int idx = tid; idx < 64*128; idx += 256){
    int k = idx >> 7, j = idx & 127;
    Uzr[idx] = (j < 64) ? Wlz[(64+k)*64 + j] : Wlr[(64+k)*64 + (j-64)];
  }
  for (int idx = tid; idx < 64*64; idx += 256){
    int k = idx >> 6, j = idx & 63;
    Uh[idx] = Wlh[(64+k)*64 + j];
  }
  if (tid < 192){
    if (tid < 128){
      int j = tid & 63;
      const float* W  = (tid<64) ? Wlz : Wlr;
      const float* Wc = (tid<64) ? Wcz : Wcr;
      const float* bc = (tid<64) ? bcz : bcr;
      const float* bl = (tid<64) ? blz : blr;
      float u = 0.f, cc = 0.f;
      for (int k=0;k<64;++k){ float w = W[k*64+j]; u = fmaf(Wc[k], w, u); cc = fmaf(bc[k], w, cc); }
      uzr[tid] = u; czr[tid] = cc + bl[j];
    } else {
      int j = tid - 128;
      float u = 0.f, cc = 0.f;
      for (int k=0;k<64;++k){ float w = Wlh[k*64+j]; u = fmaf(Wch[k], w, u); cc = fmaf(bch[k], w, cc); }
      uh2[j] = u; ch2[j] = cc + blh[j];
    }
  }
  int pbase = blockIdx.x*64;
  for (int idx = tid; idx < 64*20; idx += 256){
    int r = idx/20, t = idx - 20*r;
    int p = pbase + r; int b = p/NN, n = p - b*NN;
    Ssm[idx] = g_S[n*BT + b*TT + t];
  }
  __syncthreads();

  int pA = pbase + g,      pB = pbase + 32 + g;
  int bA = pA/NN, nA = pA - bA*NN;
  int bB = pB/NN, nB = pB - bB*NN;
  int rA = g, rB = g + 32;
  const float* HsmA = Hsm + rA*HS;
  const float* HsmB = Hsm + rB*HS;
  float* outA = out + ((size_t)(bA*TT)*NN + nA)*72 + 8 + 4*q;
  float* outB = out + ((size_t)(bB*TT)*NN + nB)*72 + 8 + 4*q;

  float hA[8], hB[8], zA[8], zB[8];

  // ---- step t=0: H=0, both matvecs vanish ----
  {
    float sA = Ssm[rA*20], sB = Ssm[rB*20];
    #pragma unroll
    for (int i=0;i<8;++i){
      int col = (i<4) ? (4*q + i) : (32 + 4*q + (i-4));
      float z_A = sigm(fmaf(sA, uzr[col], czr[col]));
      float z_B = sigm(fmaf(sB, uzr[col], czr[col]));
      float htA = tanha(fmaf(sA, uh2[col], ch2[col]));
      float htB = tanha(fmaf(sB, uh2[col], ch2[col]));
      hA[i] = (1.f - z_A)*htA;
      hB[i] = (1.f - z_B)*htB;
    }
    *(float4*)(Hsm + rA*HS + 4*q)      = make_float4(hA[0],hA[1],hA[2],hA[3]);
    *(float4*)(Hsm + rA*HS + 32 + 4*q) = make_float4(hA[4],hA[5],hA[6],hA[7]);
    *(float4*)(Hsm + rB*HS + 4*q)      = make_float4(hB[0],hB[1],hB[2],hB[3]);
    *(float4*)(Hsm + rB*HS + 32 + 4*q) = make_float4(hB[4],hB[5],hB[6],hB[7]);
    __syncwarp();
    *(float4*)(outA)      = make_float4(hA[0],hA[1],hA[2],hA[3]);
    *(float4*)(outA + 32) = make_float4(hA[4],hA[5],hA[6],hA[7]);
    *(float4*)(outB)      = make_float4(hB[0],hB[1],hB[2],hB[3]);
    *(float4*)(outB + 32) = make_float4(hB[4],hB[5],hB[6],hB[7]);
    outA += (size_t)NN*72;
    outB += (size_t)NN*72;
  }

  for (int t=1; t<TT; ++t){
    float sA = Ssm[rA*20+t], sB = Ssm[rB*20+t];
    unsigned long long aA[4], aB[4];

    // ---- Z half: pre_Z = H . Uzr[:, 0:64] ----
    matvec8(Uzr + 4*q, 128, HsmA, HsmB, aA, aB);
    #pragma unroll
    for (int i=0;i<8;++i){
      int col = (i<4) ? (4*q + i) : (32 + 4*q + (i-4));
      int ai = (i<4) ? (i>>1) : (2 + ((i-4)>>1));
      float accA = (i&1) ? hi32(aA[ai]) : lo32(aA[ai]);
      float accB = (i&1) ? hi32(aB[ai]) : lo32(aB[ai]);
      float uc = uzr[col], cc = czr[col];
      zA[i] = sigm(fmaf(sA, uc, accA + cc));
      zB[i] = sigm(fmaf(sB, uc, accB + cc));
    }

    // ---- R half: pre_R = H . Uzr[:, 64:128]; HR = H*R -> overwrite Hsm rows ----
    matvec8(Uzr + 64 + 4*q, 128, HsmA, HsmB, aA, aB);
    {
      float4 hrA0, hrA1, hrB0, hrB1;
      #pragma unroll
      for (int i=0;i<4;++i){
        int c0 = 64 + 4*q + i, c1 = 96 + 4*q + i;
        float acc0A = (i&1) ? hi32(aA[i>>1]) : lo32(aA[i>>1]);
        float acc1A = (i&1) ? hi32(aA[2+(i>>1)]) : lo32(aA[2+(i>>1)]);
        float acc0B = (i&1) ? hi32(aB[i>>1]) : lo32(aB[i>>1]);
        float acc1B = (i&1) ? hi32(aB[2+(i>>1)]) : lo32(aB[2+(i>>1)]);
        float r0A = sigm(fmaf(sA, uzr[c0], acc0A + czr[c0]));
        float r1A = sigm(fmaf(sA, uzr[c1], acc1A + czr[c1]));
        float r0B = sigm(fmaf(sB, uzr[c0], acc0B + czr[c0]));
        float r1B = sigm(fmaf(sB, uzr[c1], acc1B + czr[c1]));
        ((float*)&hrA0)[i] = hA[i]   * r0A;
        ((float*)&hrA1)[i] = hA[4+i] * r1A;
        ((float*)&hrB0)[i] = hB[i]   * r0B;
        ((float*)&hrB1)[i] = hB[4+i] * r1B;
      }
      __syncwarp();
      *(float4*)(Hsm + rA*HS + 4*q)      = hrA0;
      *(float4*)(Hsm + rA*HS + 32 + 4*q) = hrA1;
      *(float4*)(Hsm + rB*HS + 4*q)      = hrB0;
      *(float4*)(Hsm + rB*HS + 32 + 4*q) = hrB1;
      __syncwarp();
    }

    // ---- h half: pre_h = (H*R) . Uh ----
    matvec8(Uh + 4*q, 64, HsmA, HsmB, aA, aB);
    #pragma unroll
    for (int i=0;i<8;++i){
      int col = (i<4) ? (4*q + i) : (32 + 4*q + (i-4));
      int ai = (i<4) ? (i>>1) : (2 + ((i-4)>>1));
      float accA = (i&1) ? hi32(aA[ai]) : lo32(aA[ai]);
      float accB = (i&1) ? hi32(aB[ai]) : lo32(aB[ai]);
      float uc = uh2[col], cc = ch2[col];
      float htA = tanha(fmaf(sA, uc, accA + cc));
      float htB = tanha(fmaf(sB, uc, accB + cc));
      hA[i] = zA[i]*hA[i] + (1.f - zA[i])*htA;
      hB[i] = zB[i]*hB[i] + (1.f - zB[i])*htB;
    }
    __syncwarp();
    *(float4*)(Hsm + rA*HS + 4*q)      = make_float4(hA[0],hA[1],hA[2],hA[3]);
    *(float4*)(Hsm + rA*HS + 32 + 4*q) = make_float4(hA[4],hA[5],hA[6],hA[7]);
    *(float4*)(Hsm + rB*HS + 4*q)      = make_float4(hB[0],hB[1],hB[2],hB[3]);
    *(float4*)(Hsm + rB*HS + 32 + 4*q) = make_float4(hB[4],hB[5],hB[6],hB[7]);
    __syncwarp();
    *(float4*)(outA)      = make_float4(hA[0],hA[1],hA[2],hA[3]);
    *(float4*)(outA + 32) = make_float4(hA[4],hA[5],hA[6],hA[7]);
    *(float4*)(outB)      = make_float4(hB[0],hB[1],hB[2],hB[3]);
    *(float4*)(outB + 32) = make_float4(hB[4],hB[5],hB[6],hB[7]);
    outA += (size_t)NN*72;
    outB += (size_t)NN*72;
  }
}

extern "C" void kernel_launch(void* const* d_in, const int* in_sizes, int n_in,
                              void* d_out, int out_size) {
  const float* obs = (const float*)d_in[0];
  const int* ei32 = (const int*)d_in[1];
  int E = in_sizes[1] / 2;
  if (E > MAXE) E = MAXE;
  float* out = (float*)d_out;

  const int SMB = (64*128 + 64*64 + 128+128+64+64 + 64*20 + 64*HS)*4;  // 74240 B
  cudaFuncSetAttribute(k_gru, cudaFuncAttributeMaxDynamicSharedMemorySize, SMB);

  k_detect<<<1, 64>>>(ei32);
  k_init<<<(NN+255)/256, 256>>>();
  k_obs<<<(BT*NN+255)/256, 256>>>(obs, out);
  k_count<<<(E+255)/256, 256>>>(ei32, E);
  k_dinv<<<(NN+255)/256, 256>>>();
  k_scan<<<1, 256>>>();
  k_fill<<<(E+255)/256, 256>>>(ei32, E);
  k_spmm<<<(NN*5*32+255)/256, 256>>>();
  k_gru<<<(BB*NN)/64, 256, SMB>>>(
    (const float*)d_in[2], (const float*)d_in[3], (const float*)d_in[4], (const float*)d_in[5],
    (const float*)d_in[6], (const float*)d_in[7], (const float*)d_in[8], (const float*)d_in[9],
    (const float*)d_in[10], (const float*)d_in[11], (const float*)d_in[12], (const float*)d_in[13],
    out);
}

// round 10
// speedup vs baseline: 2.0414x; 1.9550x over previous
#include <cuda_runtime.h>
#include <cuda_bf16.h>
#include <cstdint>

#define NN 10000
#define BB 8
#define TT 20
#define FF 9
#define MAXE 160000
#define BT (BB*TT)   // 160

// ---------------- scratch ----------------
__device__ float g_X[NN*BT];
__device__ float g_S[NN*BT];
__device__ float g_dinv[NN];
__device__ int   g_cnt[NN];
__device__ int   g_fill[NN];
__device__ int   g_row[NN];
__device__ int2  g_ev[MAXE];
__device__ int   g_is64;

__device__ __forceinline__ float sigm(float x){ return __fdividef(1.f, 1.f + __expf(-x)); }
__device__ __forceinline__ float tanha(float x){ return 1.f - __fdividef(2.f, __expf(2.f*x) + 1.f); }

// ---------------- prep kernels (unchanged, passing since R6) ----------------
__global__ void k_detect(const int* __restrict__ w){
  int i = threadIdx.x;
  int v = w[2*i+1];
  unsigned b = __ballot_sync(0xffffffffu, v == 0);
  __shared__ int ok[2];
  if ((i & 31) == 0) ok[i >> 5] = (b == 0xffffffffu);
  __syncthreads();
  if (i == 0) g_is64 = (ok[0] && ok[1]) ? 1 : 0;
}
__global__ void k_init(){
  int i = blockIdx.x*blockDim.x + threadIdx.x;
  if (i < NN){ g_cnt[i]=0; g_fill[i]=0; }
}
__global__ void k_obs(const float* __restrict__ obs, float* __restrict__ out){
  int idx = blockIdx.x*blockDim.x + threadIdx.x;
  if (idx >= BT*NN) return;
  const float* r = obs + (size_t)idx*FF;
  float v[9];
  #pragma unroll
  for (int f=0; f<9; ++f) v[f] = r[f];
  float* o = out + (size_t)idx*72;
  *(float4*)(o)   = make_float4(v[0],v[1],v[2],v[3]);
  *(float4*)(o+4) = make_float4(v[4],v[5],v[6],v[7]);
  int bt = idx / NN, n = idx - bt*NN;
  g_X[n*BT + bt] = v[8];
}
__device__ __forceinline__ int edge_at(const int* w, int is64, int idx){
  return is64 ? w[2*idx] : w[idx];
}
__global__ void k_count(const int* __restrict__ w, int E){
  int e = blockIdx.x*blockDim.x + threadIdx.x;
  if (e >= E) return;
  int d = edge_at(w, g_is64, E + e);
  if ((unsigned)d < NN) atomicAdd(&g_cnt[d], 1);
}
__global__ void k_dinv(){
  int n = blockIdx.x*blockDim.x + threadIdx.x;
  if (n < NN) g_dinv[n] = rsqrtf((float)(g_cnt[n] + 1));
}
__global__ void k_scan(){
  __shared__ int sums[256];
  int tid = threadIdx.x;
  const int CH = 40;
  int base = tid*CH, s = 0;
  for (int i=0;i<CH;++i){ int ix = base+i; if (ix<NN) s += g_cnt[ix]; }
  sums[tid]=s; __syncthreads();
  for (int off=1; off<256; off<<=1){
    int v = (tid>=off) ? sums[tid-off] : 0;
    __syncthreads();
    sums[tid] += v;
    __syncthreads();
  }
  int run = (tid>0) ? sums[tid-1] : 0;
  for (int i=0;i<CH;++i){ int ix=base+i; if (ix<NN){ g_row[ix]=run; run += g_cnt[ix]; } }
}
__global__ void k_fill(const int* __restrict__ w, int E){
  int e = blockIdx.x*blockDim.x + threadIdx.x;
  if (e >= E) return;
  int is64 = g_is64;
  int sN = edge_at(w, is64, e);
  int d  = edge_at(w, is64, E + e);
  if ((unsigned)sN >= NN || (unsigned)d >= NN) return;
  int pos = g_row[d] + atomicAdd(&g_fill[d], 1);
  g_ev[pos] = make_int2(sN, __float_as_int(g_dinv[sN]*g_dinv[d]));
}
__global__ void k_spmm(){
  int w = (blockIdx.x*blockDim.x + threadIdx.x) >> 5;
  int lane = threadIdx.x & 31;
  if (w >= NN*5) return;
  int n = w/5, c = (w - 5*n)*32 + lane;
  float dn = g_dinv[n];
  float acc = dn*dn*g_X[n*BT + c];
  int st = g_row[n], en = st + g_cnt[n];
  for (int i=st; i<en; ++i){
    int2 ev = g_ev[i];
    acc = fmaf(__int_as_float(ev.y), g_X[ev.x*BT + c], acc);
  }
  g_S[n*BT + c] = acc;
}

// ---------------- HMMA GRU ----------------
// Storage word-position for bf16 pair p (cols 2p,2p+1), fragment-friendly:
// q = 8*(p&3) + (p>>3) + 4*((p>>2)&1).  LDS.128 at 8*tig       -> a0/b0 kt=0..3
//                                       LDS.128 at 8*tig + 4   -> a2/b1 kt=0..3
__device__ __forceinline__ int qmap(int p){ return 8*(p&3) + (p>>3) + 4*((p>>2)&1); }

__device__ __forceinline__ uint32_t bf2pack(float lo_elem, float hi_elem){
  uint32_t r;
  asm("cvt.rn.bf16x2.f32 %0, %1, %2;" : "=r"(r) : "f"(hi_elem), "f"(lo_elem));
  return r;
}
__device__ __forceinline__ float bfhi(float x){
  return __bfloat162float(__float2bfloat16(x));
}
__device__ __forceinline__ void mma16816(float d[4],
    uint32_t a0, uint32_t a1, uint32_t a2, uint32_t a3, uint32_t b0, uint32_t b1){
  asm volatile("mma.sync.aligned.m16n8k16.row.col.f32.bf16.bf16.f32 "
    "{%0,%1,%2,%3}, {%4,%5,%6,%7}, {%8,%9}, {%0,%1,%2,%3};"
    : "+f"(d[0]), "+f"(d[1]), "+f"(d[2]), "+f"(d[3])
    : "r"(a0), "r"(a1), "r"(a2), "r"(a3), "r"(b0), "r"(b1));
}

// SMEM offsets in 4-byte words
#define OFF_B1HI 0
#define OFF_B1LO 4608
#define OFF_B2HI 9216
#define OFF_B2LO 11520
#define OFF_A1HI 13824
#define OFF_A1LO 16128
#define OFF_A2HI 18432
#define OFF_A2LO 20736
#define OFF_S    23040
#define OFF_UZR  24384
#define OFF_CZR  24512
#define OFF_UH   24640
#define OFF_CH   24704
#define SM_WORDS 24768   // 99072 bytes

// one 8-nchunk matvec pass: acc[n][0..3] += A(16x64) @ B(64, 8*(nchBase+n)..)
__device__ __forceinline__ void mv_pass(const uint32_t* __restrict__ Bhi,
                                        const uint32_t* __restrict__ Blo,
                                        const uint4* Ah, const uint4* Al,
                                        float acc[8][4], int g, int tig, int nchBase){
  #pragma unroll
  for (int n=0;n<8;++n){
    const uint32_t* bh = Bhi + (8*(nchBase+n)+g)*36 + 8*tig;
    const uint32_t* bl = Blo + (8*(nchBase+n)+g)*36 + 8*tig;
    uint4 bh0 = *(const uint4*)bh;
    uint4 bh1 = *(const uint4*)(bh+4);
    uint4 bl0 = *(const uint4*)bl;
    uint4 bl1 = *(const uint4*)(bl+4);
    const uint32_t* bh0p = (const uint32_t*)&bh0;
    const uint32_t* bh1p = (const uint32_t*)&bh1;
    const uint32_t* bl0p = (const uint32_t*)&bl0;
    const uint32_t* bl1p = (const uint32_t*)&bl1;
    #pragma unroll
    for (int kt=0;kt<4;++kt){
      const uint32_t* a0 = (const uint32_t*)&Ah[0];
      const uint32_t* a1 = (const uint32_t*)&Ah[1];
      const uint32_t* a2 = (const uint32_t*)&Ah[2];
      const uint32_t* a3 = (const uint32_t*)&Ah[3];
      const uint32_t* l0 = (const uint32_t*)&Al[0];
      const uint32_t* l1 = (const uint32_t*)&Al[1];
      const uint32_t* l2 = (const uint32_t*)&Al[2];
      const uint32_t* l3 = (const uint32_t*)&Al[3];
      mma16816(acc[n], a0[kt], a1[kt], a2[kt], a3[kt], bh0p[kt], bh1p[kt]);
      mma16816(acc[n], l0[kt], l1[kt], l2[kt], l3[kt], bh0p[kt], bh1p[kt]);
      mma16816(acc[n], a0[kt], a1[kt], a2[kt], a3[kt], bl0p[kt], bl1p[kt]);
    }
  }
}

__device__ __forceinline__ void load_afrag(const uint32_t* __restrict__ M,
                                           int r0, int r1, int tig, uint4* A){
  A[0] = *(const uint4*)(M + r0*36 + 8*tig);      // a0: kt 0..3
  A[1] = *(const uint4*)(M + r1*36 + 8*tig);      // a1
  A[2] = *(const uint4*)(M + r0*36 + 8*tig + 4);  // a2
  A[3] = *(const uint4*)(M + r1*36 + 8*tig + 4);  // a3
}

// pack v[0..3] (D layout: d0=(r0,c0) d1=(r0,c1) d2=(r1,c0) d3=(r1,c1)) as bf16
// hi/lo pairs into fragment storage at rows r0,r1, pair p=4n+tig
__device__ __forceinline__ void store_frag_pair(uint32_t* __restrict__ Mhi,
                                                uint32_t* __restrict__ Mlo,
                                                int r0, int r1, int n, int tig,
                                                const float* v){
  int q = 8*tig + (n>>1) + 4*(n&1);
  uint32_t h0 = bf2pack(bfhi(v[0]), bfhi(v[1]));
  uint32_t l0 = bf2pack(v[0]-bfhi(v[0]), v[1]-bfhi(v[1]));
  uint32_t h1 = bf2pack(bfhi(v[2]), bfhi(v[3]));
  uint32_t l1 = bf2pack(v[2]-bfhi(v[2]), v[3]-bfhi(v[3]));
  Mhi[r0*36 + q] = h0;  Mlo[r0*36 + q] = l0;
  Mhi[r1*36 + q] = h1;  Mlo[r1*36 + q] = l1;
}

__global__ void __launch_bounds__(128,2) k_hmma(
   const float* __restrict__ Wcz, const float* __restrict__ bcz,
   const float* __restrict__ Wlz, const float* __restrict__ blz,
   const float* __restrict__ Wcr, const float* __restrict__ bcr,
   const float* __restrict__ Wlr, const float* __restrict__ blr,
   const float* __restrict__ Wch, const float* __restrict__ bch,
   const float* __restrict__ Wlh, const float* __restrict__ blh,
   float* __restrict__ out)
{
  extern __shared__ __align__(16) uint32_t sm[];
  float* smf = (float*)sm;

  int tid = threadIdx.x, lane = tid & 31, w = tid >> 5;
  int g = lane >> 2, tig = lane & 3;

  // ---- prologue: weights -> bf16 hi/lo fragment layout ----
  for (int idx = tid; idx < 128*32; idx += 128){
    int n = idx >> 5, p = idx & 31;
    int k0 = 2*p;
    float w0, w1;
    if (n < 64){ w0 = Wlz[(64+k0)*64 + n];  w1 = Wlz[(65+k0)*64 + n]; }
    else       { w0 = Wlr[(64+k0)*64 + n-64]; w1 = Wlr[(65+k0)*64 + n-64]; }
    float h0 = bfhi(w0), h1 = bfhi(w1);
    int q = qmap(p);
    sm[OFF_B1HI + n*36 + q] = bf2pack(h0, h1);
    sm[OFF_B1LO + n*36 + q] = bf2pack(w0-h0, w1-h1);
  }
  for (int idx = tid; idx < 64*32; idx += 128){
    int n = idx >> 5, p = idx & 31;
    int k0 = 2*p;
    float w0 = Wlh[(64+k0)*64 + n], w1 = Wlh[(65+k0)*64 + n];
    float h0 = bfhi(w0), h1 = bfhi(w1);
    int q = qmap(p);
    sm[OFF_B2HI + n*36 + q] = bf2pack(h0, h1);
    sm[OFF_B2LO + n*36 + q] = bf2pack(w0-h0, w1-h1);
  }
  for (int jj = tid; jj < 192; jj += 128){
    if (jj < 128){
      int j = jj & 63;
      const float* W  = (jj<64) ? Wlz : Wlr;
      const float* Wc = (jj<64) ? Wcz : Wcr;
      const float* bc = (jj<64) ? bcz : bcr;
      const float* bl = (jj<64) ? blz : blr;
      float u = 0.f, cc = 0.f;
      for (int k=0;k<64;++k){ float ww = W[k*64+j]; u = fmaf(Wc[k], ww, u); cc = fmaf(bc[k], ww, cc); }
      smf[OFF_UZR + jj] = u; smf[OFF_CZR + jj] = cc + bl[j];
    } else {
      int j = jj - 128;
      float u = 0.f, cc = 0.f;
      for (int k=0;k<64;++k){ float ww = Wlh[k*64+j]; u = fmaf(Wch[k], ww, u); cc = fmaf(bch[k], ww, cc); }
      smf[OFF_UH + j] = u; smf[OFF_CH + j] = cc + blh[j];
    }
  }
  int pbase = blockIdx.x*64;
  for (int idx = tid; idx < 64*20; idx += 128){
    int r = idx/20, t = idx - 20*r;
    int p = pbase + r; int b = p/NN, n = p - b*NN;
    smf[OFF_S + r*21 + t] = g_S[n*BT + b*TT + t];
  }
  __syncthreads();

  // warp-local rows
  int r0 = 16*w + g, r1 = r0 + 8;
  int P0 = pbase + r0, P1 = pbase + r1;
  int b0 = P0/NN, n0 = P0 - b0*NN;
  int b1 = P1/NN, n1 = P1 - b1*NN;
  float* out0 = out + ((size_t)(b0*TT)*NN + n0)*72 + 8 + 2*tig;
  float* out1 = out + ((size_t)(b1*TT)*NN + n1)*72 + 8 + 2*tig;
  const float* S0 = smf + OFF_S + r0*21;
  const float* S1 = smf + OFF_S + r1*21;

  const float* uzr = smf + OFF_UZR;
  const float* czr = smf + OFF_CZR;
  const float* uh2 = smf + OFF_UH;
  const float* ch2 = smf + OFF_CH;

  float h[8][4];   // D layout per nchunk

  // ---- t = 0: H = 0, closed form ----
  {
    float s0 = S0[0], s1 = S1[0];
    #pragma unroll
    for (int n=0;n<8;++n){
      #pragma unroll
      for (int j=0;j<4;++j){
        int c = 8*n + 2*tig + (j&1);
        float s = (j<2) ? s0 : s1;
        float z  = sigm(fmaf(s, uzr[c], czr[c]));
        float ht = tanha(fmaf(s, uh2[c], ch2[c]));
        h[n][j] = (1.f - z)*ht;
      }
      *(float2*)(out0 + 8*n) = make_float2(h[n][0], h[n][1]);
      *(float2*)(out1 + 8*n) = make_float2(h[n][2], h[n][3]);
      store_frag_pair(sm + OFF_A1HI, sm + OFF_A1LO, r0, r1, n, tig, h[n]);
    }
    out0 += (size_t)NN*72;
    out1 += (size_t)NN*72;
    __syncwarp();
  }

  for (int t=1; t<TT; ++t){
    float s0 = S0[t], s1 = S1[t];
    uint4 Ah[4], Al[4];
    load_afrag(sm + OFF_A1HI, r0, r1, tig, Ah);
    load_afrag(sm + OFF_A1LO, r0, r1, tig, Al);

    // ---- pass 1a: z (cols 0..63) ----
    float acc[8][4];
    #pragma unroll
    for (int n=0;n<8;++n){ acc[n][0]=0.f; acc[n][1]=0.f; acc[n][2]=0.f; acc[n][3]=0.f; }
    mv_pass(sm + OFF_B1HI, sm + OFF_B1LO, Ah, Al, acc, g, tig, 0);
    float z[8][4];
    #pragma unroll
    for (int n=0;n<8;++n){
      #pragma unroll
      for (int j=0;j<4;++j){
        int c = 8*n + 2*tig + (j&1);
        float s = (j<2) ? s0 : s1;
        z[n][j] = sigm(acc[n][j] + fmaf(s, uzr[c], czr[c]));
      }
    }

    // ---- pass 1b: r (cols 64..127) -> HR -> A2 ----
    #pragma unroll
    for (int n=0;n<8;++n){ acc[n][0]=0.f; acc[n][1]=0.f; acc[n][2]=0.f; acc[n][3]=0.f; }
    mv_pass(sm + OFF_B1HI, sm + OFF_B1LO, Ah, Al, acc, g, tig, 8);
    #pragma unroll
    for (int n=0;n<8;++n){
      float hr[4];
      #pragma unroll
      for (int j=0;j<4;++j){
        int c = 64 + 8*n + 2*tig + (j&1);
        float s = (j<2) ? s0 : s1;
        float r = sigm(acc[n][j] + fmaf(s, uzr[c], czr[c]));
        hr[j] = h[n][j] * r;
      }
      store_frag_pair(sm + OFF_A2HI, sm + OFF_A2LO, r0, r1, n, tig, hr);
    }
    __syncwarp();

    // ---- pass 2: htil = HR . Uh; blend; out; H -> A1 ----
    load_afrag(sm + OFF_A2HI, r0, r1, tig, Ah);
    load_afrag(sm + OFF_A2LO, r0, r1, tig, Al);
    #pragma unroll
    for (int n=0;n<8;++n){ acc[n][0]=0.f; acc[n][1]=0.f; acc[n][2]=0.f; acc[n][3]=0.f; }
    mv_pass(sm + OFF_B2HI, sm + OFF_B2LO, Ah, Al, acc, g, tig, 0);
    #pragma unroll
    for (int n=0;n<8;++n){
      #pragma unroll
      for (int j=0;j<4;++j){
        int c = 8*n + 2*tig + (j&1);
        float s = (j<2) ? s0 : s1;
        float ht = tanha(acc[n][j] + fmaf(s, uh2[c], ch2[c]));
        h[n][j] = z[n][j]*h[n][j] + (1.f - z[n][j])*ht;
      }
      *(float2*)(out0 + 8*n) = make_float2(h[n][0], h[n][1]);
      *(float2*)(out1 + 8*n) = make_float2(h[n][2], h[n][3]);
      store_frag_pair(sm + OFF_A1HI, sm + OFF_A1LO, r0, r1, n, tig, h[n]);
    }
    out0 += (size_t)NN*72;
    out1 += (size_t)NN*72;
    __syncwarp();
  }
}

extern "C" void kernel_launch(void* const* d_in, const int* in_sizes, int n_in,
                              void* d_out, int out_size) {
  const float* obs = (const float*)d_in[0];
  const int* ei32 = (const int*)d_in[1];
  int E = in_sizes[1] / 2;
  if (E > MAXE) E = MAXE;
  float* out = (float*)d_out;

  const int SMB = SM_WORDS*4;   // 99072 B
  cudaFuncSetAttribute(k_hmma, cudaFuncAttributeMaxDynamicSharedMemorySize, SMB);

  k_detect<<<1, 64>>>(ei32);
  k_init<<<(NN+255)/256, 256>>>();
  k_obs<<<(BT*NN+255)/256, 256>>>(obs, out);
  k_count<<<(E+255)/256, 256>>>(ei32, E);
  k_dinv<<<(NN+255)/256, 256>>>();
  k_scan<<<1, 256>>>();
  k_fill<<<(E+255)/256, 256>>>(ei32, E);
  k_spmm<<<(NN*5*32+255)/256, 256>>>();
  k_hmma<<<(BB*NN)/64, 128, SMB>>>(
    (const float*)d_in[2], (const float*)d_in[3], (const float*)d_in[4], (const float*)d_in[5],
    (const float*)d_in[6], (const float*)d_in[7], (const float*)d_in[8], (const float*)d_in[9],
    (const float*)d_in[10], (const float*)d_in[11], (const float*)d_in[12], (const float*)d_in[13],
    out);
}

// round 11
// speedup vs baseline: 2.5138x; 1.2314x over previous
#include <cuda_runtime.h>
#include <cuda_bf16.h>
#include <cstdint>

#define NN 10000
#define BB 8
#define TT 20
#define FF 9
#define MAXE 160000
#define BT (BB*TT)   // 160

// ---------------- scratch ----------------
__device__ float g_X[NN*BT];
__device__ float g_S[NN*BT];
__device__ float g_dinv[NN];
__device__ int   g_cnt[NN];
__device__ int   g_fill[NN];
__device__ int   g_row[NN];
__device__ int2  g_ev[MAXE];
__device__ int   g_is64;

__device__ __forceinline__ float sigm(float x){ return __fdividef(1.f, 1.f + __expf(-x)); }
__device__ __forceinline__ float tanha(float x){ return 1.f - __fdividef(2.f, __expf(2.f*x) + 1.f); }

// ---------------- prep kernels (unchanged, passing since R6) ----------------
__global__ void k_detect(const int* __restrict__ w){
  int i = threadIdx.x;
  int v = w[2*i+1];
  unsigned b = __ballot_sync(0xffffffffu, v == 0);
  __shared__ int ok[2];
  if ((i & 31) == 0) ok[i >> 5] = (b == 0xffffffffu);
  __syncthreads();
  if (i == 0) g_is64 = (ok[0] && ok[1]) ? 1 : 0;
}
__global__ void k_init(){
  int i = blockIdx.x*blockDim.x + threadIdx.x;
  if (i < NN){ g_cnt[i]=0; g_fill[i]=0; }
}
__global__ void k_obs(const float* __restrict__ obs, float* __restrict__ out){
  int idx = blockIdx.x*blockDim.x + threadIdx.x;
  if (idx >= BT*NN) return;
  const float* r = obs + (size_t)idx*FF;
  float v[9];
  #pragma unroll
  for (int f=0; f<9; ++f) v[f] = r[f];
  float* o = out + (size_t)idx*72;
  *(float4*)(o)   = make_float4(v[0],v[1],v[2],v[3]);
  *(float4*)(o+4) = make_float4(v[4],v[5],v[6],v[7]);
  int bt = idx / NN, n = idx - bt*NN;
  g_X[n*BT + bt] = v[8];
}
__device__ __forceinline__ int edge_at(const int* w, int is64, int idx){
  return is64 ? w[2*idx] : w[idx];
}
__global__ void k_count(const int* __restrict__ w, int E){
  int e = blockIdx.x*blockDim.x + threadIdx.x;
  if (e >= E) return;
  int d = edge_at(w, g_is64, E + e);
  if ((unsigned)d < NN) atomicAdd(&g_cnt[d], 1);
}
__global__ void k_dinv(){
  int n = blockIdx.x*blockDim.x + threadIdx.x;
  if (n < NN) g_dinv[n] = rsqrtf((float)(g_cnt[n] + 1));
}
__global__ void k_scan(){
  __shared__ int sums[256];
  int tid = threadIdx.x;
  const int CH = 40;
  int base = tid*CH, s = 0;
  for (int i=0;i<CH;++i){ int ix = base+i; if (ix<NN) s += g_cnt[ix]; }
  sums[tid]=s; __syncthreads();
  for (int off=1; off<256; off<<=1){
    int v = (tid>=off) ? sums[tid-off] : 0;
    __syncthreads();
    sums[tid] += v;
    __syncthreads();
  }
  int run = (tid>0) ? sums[tid-1] : 0;
  for (int i=0;i<CH;++i){ int ix=base+i; if (ix<NN){ g_row[ix]=run; run += g_cnt[ix]; } }
}
__global__ void k_fill(const int* __restrict__ w, int E){
  int e = blockIdx.x*blockDim.x + threadIdx.x;
  if (e >= E) return;
  int is64 = g_is64;
  int sN = edge_at(w, is64, e);
  int d  = edge_at(w, is64, E + e);
  if ((unsigned)sN >= NN || (unsigned)d >= NN) return;
  int pos = g_row[d] + atomicAdd(&g_fill[d], 1);
  g_ev[pos] = make_int2(sN, __float_as_int(g_dinv[sN]*g_dinv[d]));
}
__global__ void k_spmm(){
  int w = (blockIdx.x*blockDim.x + threadIdx.x) >> 5;
  int lane = threadIdx.x & 31;
  if (w >= NN*5) return;
  int n = w/5, c = (w - 5*n)*32 + lane;
  float dn = g_dinv[n];
  float acc = dn*dn*g_X[n*BT + c];
  int st = g_row[n], en = st + g_cnt[n];
  for (int i=st; i<en; ++i){
    int2 ev = g_ev[i];
    acc = fmaf(__int_as_float(ev.y), g_X[ev.x*BT + c], acc);
  }
  g_S[n*BT + c] = acc;
}

// ---------------- HMMA GRU (register-resident state) ----------------
// Weight storage word-position for bf16 pair p (cols 2p,2p+1), fragment-friendly:
// q = 8*(p&3) + (p>>3) + 4*((p>>2)&1)
__device__ __forceinline__ int qmap(int p){ return 8*(p&3) + (p>>3) + 4*((p>>2)&1); }

__device__ __forceinline__ uint32_t bf2pack(float lo_elem, float hi_elem){
  uint32_t r;
  asm("cvt.rn.bf16x2.f32 %0, %1, %2;" : "=r"(r) : "f"(hi_elem), "f"(lo_elem));
  return r;
}
__device__ __forceinline__ float bfhi(float x){
  return __bfloat162float(__float2bfloat16(x));
}
__device__ __forceinline__ void mma16816(float d[4],
    uint32_t a0, uint32_t a1, uint32_t a2, uint32_t a3, uint32_t b0, uint32_t b1){
  asm volatile("mma.sync.aligned.m16n8k16.row.col.f32.bf16.bf16.f32 "
    "{%0,%1,%2,%3}, {%4,%5,%6,%7}, {%8,%9}, {%0,%1,%2,%3};"
    : "+f"(d[0]), "+f"(d[1]), "+f"(d[2]), "+f"(d[3])
    : "r"(a0), "r"(a1), "r"(a2), "r"(a3), "r"(b0), "r"(b1));
}

// SMEM offsets in 4-byte words
#define OFF_B1HI 0
#define OFF_B1LO 4608
#define OFF_B2HI 9216
#define OFF_B2LO 11520
#define OFF_S    13824
#define OFF_UZR  15168
#define OFF_CZR  15296
#define OFF_UH   15424
#define OFF_CH   15488
#define SM_WORDS 15552   // 62208 bytes

// one 8-nchunk matvec pass with register A fragments (3-term bf16 split)
__device__ __forceinline__ void mv_pass(const uint32_t* __restrict__ Bhi,
                                        const uint32_t* __restrict__ Blo,
                                        const uint32_t* Ah, const uint32_t* Al,
                                        float acc[8][4], int g, int tig, int nchBase){
  #pragma unroll
  for (int n=0;n<8;++n){
    const uint32_t* bh = Bhi + (8*(nchBase+n)+g)*36 + 8*tig;
    const uint32_t* bl = Blo + (8*(nchBase+n)+g)*36 + 8*tig;
    uint4 bh0 = *(const uint4*)bh;
    uint4 bh1 = *(const uint4*)(bh+4);
    uint4 bl0 = *(const uint4*)bl;
    uint4 bl1 = *(const uint4*)(bl+4);
    const uint32_t* bh0p = (const uint32_t*)&bh0;
    const uint32_t* bh1p = (const uint32_t*)&bh1;
    const uint32_t* bl0p = (const uint32_t*)&bl0;
    const uint32_t* bl1p = (const uint32_t*)&bl1;
    #pragma unroll
    for (int kt=0;kt<4;++kt){
      mma16816(acc[n], Ah[4*kt], Ah[4*kt+1], Ah[4*kt+2], Ah[4*kt+3], bh0p[kt], bh1p[kt]);
      mma16816(acc[n], Al[4*kt], Al[4*kt+1], Al[4*kt+2], Al[4*kt+3], bh0p[kt], bh1p[kt]);
      mma16816(acc[n], Ah[4*kt], Ah[4*kt+1], Ah[4*kt+2], Ah[4*kt+3], bl0p[kt], bl1p[kt]);
    }
  }
}

// pack fp32 state (D layout v[8][4]) into A fragments: Ah/Al[16]
// a0(kt)=pack(v[2kt][0],v[2kt][1]) a1=..[2],[3]  a2/a3 from n=2kt+1
__device__ __forceinline__ void pack_state(const float v[8][4], uint32_t* Ah, uint32_t* Al){
  #pragma unroll
  for (int kt=0;kt<4;++kt){
    #pragma unroll
    for (int half=0; half<2; ++half){
      int n = 2*kt + half;
      float h0=bfhi(v[n][0]), h1=bfhi(v[n][1]), h2=bfhi(v[n][2]), h3=bfhi(v[n][3]);
      Ah[4*kt+2*half]   = bf2pack(h0, h1);
      Ah[4*kt+2*half+1] = bf2pack(h2, h3);
      Al[4*kt+2*half]   = bf2pack(v[n][0]-h0, v[n][1]-h1);
      Al[4*kt+2*half+1] = bf2pack(v[n][2]-h2, v[n][3]-h3);
    }
  }
}

__global__ void __launch_bounds__(128,3) k_hmma(
   const float* __restrict__ Wcz, const float* __restrict__ bcz,
   const float* __restrict__ Wlz, const float* __restrict__ blz,
   const float* __restrict__ Wcr, const float* __restrict__ bcr,
   const float* __restrict__ Wlr, const float* __restrict__ blr,
   const float* __restrict__ Wch, const float* __restrict__ bch,
   const float* __restrict__ Wlh, const float* __restrict__ blh,
   float* __restrict__ out)
{
  extern __shared__ __align__(16) uint32_t sm[];
  float* smf = (float*)sm;

  int tid = threadIdx.x, lane = tid & 31, w = tid >> 5;
  int g = lane >> 2, tig = lane & 3;

  // ---- prologue: weights -> bf16 hi/lo fragment layout ----
  for (int idx = tid; idx < 128*32; idx += 128){
    int n = idx >> 5, p = idx & 31;
    int k0 = 2*p;
    float w0, w1;
    if (n < 64){ w0 = Wlz[(64+k0)*64 + n];  w1 = Wlz[(65+k0)*64 + n]; }
    else       { w0 = Wlr[(64+k0)*64 + n-64]; w1 = Wlr[(65+k0)*64 + n-64]; }
    float h0 = bfhi(w0), h1 = bfhi(w1);
    int q = qmap(p);
    sm[OFF_B1HI + n*36 + q] = bf2pack(h0, h1);
    sm[OFF_B1LO + n*36 + q] = bf2pack(w0-h0, w1-h1);
  }
  for (int idx = tid; idx < 64*32; idx += 128){
    int n = idx >> 5, p = idx & 31;
    int k0 = 2*p;
    float w0 = Wlh[(64+k0)*64 + n], w1 = Wlh[(65+k0)*64 + n];
    float h0 = bfhi(w0), h1 = bfhi(w1);
    int q = qmap(p);
    sm[OFF_B2HI + n*36 + q] = bf2pack(h0, h1);
    sm[OFF_B2LO + n*36 + q] = bf2pack(w0-h0, w1-h1);
  }
  for (int jj = tid; jj < 192; jj += 128){
    if (jj < 128){
      int j = jj & 63;
      const float* W  = (jj<64) ? Wlz : Wlr;
      const float* Wc = (jj<64) ? Wcz : Wcr;
      const float* bc = (jj<64) ? bcz : bcr;
      const float* bl = (jj<64) ? blz : blr;
      float u = 0.f, cc = 0.f;
      for (int k=0;k<64;++k){ float ww = W[k*64+j]; u = fmaf(Wc[k], ww, u); cc = fmaf(bc[k], ww, cc); }
      smf[OFF_UZR + jj] = u; smf[OFF_CZR + jj] = cc + bl[j];
    } else {
      int j = jj - 128;
      float u = 0.f, cc = 0.f;
      for (int k=0;k<64;++k){ float ww = Wlh[k*64+j]; u = fmaf(Wch[k], ww, u); cc = fmaf(bch[k], ww, cc); }
      smf[OFF_UH + j] = u; smf[OFF_CH + j] = cc + blh[j];
    }
  }
  int pbase = blockIdx.x*64;
  for (int idx = tid; idx < 64*20; idx += 128){
    int r = idx/20, t = idx - 20*r;
    int p = pbase + r; int b = p/NN, n = p - b*NN;
    smf[OFF_S + r*21 + t] = g_S[n*BT + b*TT + t];
  }
  __syncthreads();

  // warp-local rows
  int r0 = 16*w + g, r1 = r0 + 8;
  int P0 = pbase + r0, P1 = pbase + r1;
  int b0 = P0/NN, n0 = P0 - b0*NN;
  int b1 = P1/NN, n1 = P1 - b1*NN;
  float* out0 = out + ((size_t)(b0*TT)*NN + n0)*72 + 8 + 2*tig;
  float* out1 = out + ((size_t)(b1*TT)*NN + n1)*72 + 8 + 2*tig;
  const float* S0 = smf + OFF_S + r0*21;
  const float* S1 = smf + OFF_S + r1*21;

  const float2* uzr2 = (const float2*)(smf + OFF_UZR);
  const float2* czr2 = (const float2*)(smf + OFF_CZR);
  const float2* uh22 = (const float2*)(smf + OFF_UH);
  const float2* ch22 = (const float2*)(smf + OFF_CH);

  float h[8][4];
  uint32_t Ah[16], Al[16];

  // ---- t = 0: H = 0, closed form ----
  {
    float s0 = S0[0], s1 = S1[0];
    #pragma unroll
    for (int n=0;n<8;++n){
      float2 uz = uzr2[4*n+tig], cz = czr2[4*n+tig];
      float2 uh = uh22[4*n+tig], ch = ch22[4*n+tig];
      #pragma unroll
      for (int j=0;j<4;++j){
        float s = (j<2) ? s0 : s1;
        float u  = (j&1) ? uz.y : uz.x;
        float c  = (j&1) ? cz.y : cz.x;
        float uu = (j&1) ? uh.y : uh.x;
        float cc = (j&1) ? ch.y : ch.x;
        float z  = sigm(fmaf(s, u, c));
        float ht = tanha(fmaf(s, uu, cc));
        h[n][j] = (1.f - z)*ht;
      }
      *(float2*)(out0 + 8*n) = make_float2(h[n][0], h[n][1]);
      *(float2*)(out1 + 8*n) = make_float2(h[n][2], h[n][3]);
    }
    pack_state(h, Ah, Al);
    out0 += (size_t)NN*72;
    out1 += (size_t)NN*72;
  }

  for (int t=1; t<TT; ++t){
    float s0 = S0[t], s1 = S1[t];

    // ---- pass 1a: z (cols 0..63) ----
    float acc[8][4];
    #pragma unroll
    for (int n=0;n<8;++n){ acc[n][0]=0.f; acc[n][1]=0.f; acc[n][2]=0.f; acc[n][3]=0.f; }
    mv_pass(sm + OFF_B1HI, sm + OFF_B1LO, Ah, Al, acc, g, tig, 0);
    float z[8][4];
    #pragma unroll
    for (int n=0;n<8;++n){
      float2 uz = uzr2[4*n+tig], cz = czr2[4*n+tig];
      #pragma unroll
      for (int j=0;j<4;++j){
        float s = (j<2) ? s0 : s1;
        float u = (j&1) ? uz.y : uz.x;
        float c = (j&1) ? cz.y : cz.x;
        z[n][j] = sigm(acc[n][j] + fmaf(s, u, c));
      }
    }

    // ---- pass 1b: r (cols 64..127) -> HR (registers) ----
    #pragma unroll
    for (int n=0;n<8;++n){ acc[n][0]=0.f; acc[n][1]=0.f; acc[n][2]=0.f; acc[n][3]=0.f; }
    mv_pass(sm + OFF_B1HI, sm + OFF_B1LO, Ah, Al, acc, g, tig, 8);
    float hr[8][4];
    #pragma unroll
    for (int n=0;n<8;++n){
      float2 uz = uzr2[32 + 4*n+tig], cz = czr2[32 + 4*n+tig];
      #pragma unroll
      for (int j=0;j<4;++j){
        float s = (j<2) ? s0 : s1;
        float u = (j&1) ? uz.y : uz.x;
        float c = (j&1) ? cz.y : cz.x;
        float r = sigm(acc[n][j] + fmaf(s, u, c));
        hr[n][j] = h[n][j] * r;
      }
    }
    pack_state(hr, Ah, Al);   // A2 = HR, in registers

    // ---- pass 2: htil = HR . Uh; blend; out; repack H ----
    #pragma unroll
    for (int n=0;n<8;++n){ acc[n][0]=0.f; acc[n][1]=0.f; acc[n][2]=0.f; acc[n][3]=0.f; }
    mv_pass(sm + OFF_B2HI, sm + OFF_B2LO, Ah, Al, acc, g, tig, 0);
    #pragma unroll
    for (int n=0;n<8;++n){
      float2 uh = uh22[4*n+tig], ch = ch22[4*n+tig];
      #pragma unroll
      for (int j=0;j<4;++j){
        float s = (j<2) ? s0 : s1;
        float u = (j&1) ? uh.y : uh.x;
        float c = (j&1) ? ch.y : ch.x;
        float ht = tanha(acc[n][j] + fmaf(s, u, c));
        h[n][j] = z[n][j]*h[n][j] + (1.f - z[n][j])*ht;
      }
      *(float2*)(out0 + 8*n) = make_float2(h[n][0], h[n][1]);
      *(float2*)(out1 + 8*n) = make_float2(h[n][2], h[n][3]);
    }
    pack_state(h, Ah, Al);
    out0 += (size_t)NN*72;
    out1 += (size_t)NN*72;
  }
}

extern "C" void kernel_launch(void* const* d_in, const int* in_sizes, int n_in,
                              void* d_out, int out_size) {
  const float* obs = (const float*)d_in[0];
  const int* ei32 = (const int*)d_in[1];
  int E = in_sizes[1] / 2;
  if (E > MAXE) E = MAXE;
  float* out = (float*)d_out;

  const int SMB = SM_WORDS*4;   // 62208 B
  cudaFuncSetAttribute(k_hmma, cudaFuncAttributeMaxDynamicSharedMemorySize, SMB);

  k_detect<<<1, 64>>>(ei32);
  k_init<<<(NN+255)/256, 256>>>();
  k_obs<<<(BT*NN+255)/256, 256>>>(obs, out);
  k_count<<<(E+255)/256, 256>>>(ei32, E);
  k_dinv<<<(NN+255)/256, 256>>>();
  k_scan<<<1, 256>>>();
  k_fill<<<(E+255)/256, 256>>>(ei32, E);
  k_spmm<<<(NN*5*32+255)/256, 256>>>();
  k_hmma<<<(BB*NN)/64, 128, SMB>>>(
    (const float*)d_in[2], (const float*)d_in[3], (const float*)d_in[4], (const float*)d_in[5],
    (const float*)d_in[6], (const float*)d_in[7], (const float*)d_in[8], (const float*)d_in[9],
    (const float*)d_in[10], (const float*)d_in[11], (const float*)d_in[12], (const float*)d_in[13],
    out);
}

// round 12
// speedup vs baseline: 2.8527x; 1.1348x over previous
#include <cuda_runtime.h>
#include <cuda_bf16.h>
#include <cstdint>

#define NN 10000
#define BB 8
#define TT 20
#define FF 9
#define MAXE 160000
#define BT (BB*TT)   // 160

// ---------------- scratch ----------------
__device__ float g_X[NN*BT];
__device__ float g_S[NN*BT];
__device__ float g_dinv[NN];
__device__ int   g_cnt[NN];
__device__ int   g_fill[NN];
__device__ int   g_row[NN];
__device__ int2  g_ev[MAXE];
__device__ int   g_is64;

__device__ __forceinline__ float tanhap(float x){
  float y; asm("tanh.approx.f32 %0, %1;" : "=f"(y) : "f"(x)); return y;
}
__device__ __forceinline__ float sigm(float x){ return fmaf(tanhap(0.5f*x), 0.5f, 0.5f); }

// ---------------- prep kernels (fused) ----------------
__global__ void k_pre(const int* __restrict__ w){
  int i = blockIdx.x*blockDim.x + threadIdx.x;
  if (i < NN){ g_cnt[i]=0; g_fill[i]=0; }
  if (blockIdx.x==0 && threadIdx.x<32){
    int v = w[2*threadIdx.x+1] | w[2*(threadIdx.x+32)+1];
    unsigned b = __ballot_sync(0xffffffffu, v==0);
    if (threadIdx.x==0) g_is64 = (b==0xffffffffu) ? 1 : 0;
  }
}
__device__ __forceinline__ int edge_at(const int* w, int is64, int idx){
  return is64 ? w[2*idx] : w[idx];
}
__global__ void k_obs_count(const float* __restrict__ obs, float* __restrict__ out,
                            const int* __restrict__ w, int E, int obsBlocks){
  if ((int)blockIdx.x < obsBlocks){
    int idx = blockIdx.x*256 + threadIdx.x;
    if (idx >= BT*NN) return;
    const float* r = obs + (size_t)idx*FF;
    float v[9];
    #pragma unroll
    for (int f=0; f<9; ++f) v[f] = r[f];
    float* o = out + (size_t)idx*72;
    *(float4*)(o)   = make_float4(v[0],v[1],v[2],v[3]);
    *(float4*)(o+4) = make_float4(v[4],v[5],v[6],v[7]);
    int bt = idx / NN, n = idx - bt*NN;
    g_X[n*BT + bt] = v[8];
  } else {
    int e = (blockIdx.x - obsBlocks)*256 + threadIdx.x;
    if (e >= E) return;
    int d = edge_at(w, g_is64, E + e);
    if ((unsigned)d < NN) atomicAdd(&g_cnt[d], 1);
  }
}
__global__ void k_scan(){   // exclusive prefix of g_cnt -> g_row; also dinv
  __shared__ int sums[256];
  int tid = threadIdx.x;
  const int CH = 40;
  int base = tid*CH, s = 0;
  for (int i=0;i<CH;++i){
    int ix = base+i;
    if (ix<NN){ int c = g_cnt[ix]; s += c; g_dinv[ix] = rsqrtf((float)(c+1)); }
  }
  sums[tid]=s; __syncthreads();
  for (int off=1; off<256; off<<=1){
    int v = (tid>=off) ? sums[tid-off] : 0;
    __syncthreads();
    sums[tid] += v;
    __syncthreads();
  }
  int run = (tid>0) ? sums[tid-1] : 0;
  for (int i=0;i<CH;++i){ int ix=base+i; if (ix<NN){ g_row[ix]=run; run += g_cnt[ix]; } }
}
__global__ void k_fill(const int* __restrict__ w, int E){
  int e = blockIdx.x*blockDim.x + threadIdx.x;
  if (e >= E) return;
  int is64 = g_is64;
  int sN = edge_at(w, is64, e);
  int d  = edge_at(w, is64, E + e);
  if ((unsigned)sN >= NN || (unsigned)d >= NN) return;
  int pos = g_row[d] + atomicAdd(&g_fill[d], 1);
  g_ev[pos] = make_int2(sN, __float_as_int(g_dinv[sN]*g_dinv[d]));
}
__global__ void k_spmm(){
  int w = (blockIdx.x*blockDim.x + threadIdx.x) >> 5;
  int lane = threadIdx.x & 31;
  if (w >= NN*5) return;
  int n = w/5, c = (w - 5*n)*32 + lane;
  float dn = g_dinv[n];
  float acc = dn*dn*g_X[n*BT + c];
  int st = g_row[n], en = st + g_cnt[n];
  for (int i=st; i<en; ++i){
    int2 ev = g_ev[i];
    acc = fmaf(__int_as_float(ev.y), g_X[ev.x*BT + c], acc);
  }
  g_S[n*BT + c] = acc;
}

// ---------------- HMMA GRU (register-resident state) ----------------
__device__ __forceinline__ int qmap(int p){ return 8*(p&3) + (p>>3) + 4*((p>>2)&1); }

__device__ __forceinline__ uint32_t bf2pack(float lo_elem, float hi_elem){
  uint32_t r;
  asm("cvt.rn.bf16x2.f32 %0, %1, %2;" : "=r"(r) : "f"(hi_elem), "f"(lo_elem));
  return r;
}
__device__ __forceinline__ float bfhi(float x){
  return __bfloat162float(__float2bfloat16(x));
}
// pack pair (v0 -> low half, v1 -> high half) + residual pack, bit-op hi recovery
__device__ __forceinline__ void pack2(float v0, float v1, uint32_t& ph, uint32_t& pl){
  ph = bf2pack(v0, v1);
  float h0 = __uint_as_float(ph << 16);
  float h1 = __uint_as_float(ph & 0xFFFF0000u);
  pl = bf2pack(v0 - h0, v1 - h1);
}
__device__ __forceinline__ void mma16816(float d[4],
    uint32_t a0, uint32_t a1, uint32_t a2, uint32_t a3, uint32_t b0, uint32_t b1){
  asm volatile("mma.sync.aligned.m16n8k16.row.col.f32.bf16.bf16.f32 "
    "{%0,%1,%2,%3}, {%4,%5,%6,%7}, {%8,%9}, {%0,%1,%2,%3};"
    : "+f"(d[0]), "+f"(d[1]), "+f"(d[2]), "+f"(d[3])
    : "r"(a0), "r"(a1), "r"(a2), "r"(a3), "r"(b0), "r"(b1));
}
__device__ __forceinline__ void mma16816_z(float d[4],
    uint32_t a0, uint32_t a1, uint32_t a2, uint32_t a3, uint32_t b0, uint32_t b1){
  asm volatile("mma.sync.aligned.m16n8k16.row.col.f32.bf16.bf16.f32 "
    "{%0,%1,%2,%3}, {%4,%5,%6,%7}, {%8,%9}, {%10,%10,%10,%10};"
    : "=f"(d[0]), "=f"(d[1]), "=f"(d[2]), "=f"(d[3])
    : "r"(a0), "r"(a1), "r"(a2), "r"(a3), "r"(b0), "r"(b1), "f"(0.0f));
}

// SMEM offsets in 4-byte words
#define OFF_B1HI 0
#define OFF_B1LO 4608
#define OFF_B2HI 9216
#define OFF_B2LO 11520
#define OFF_S    13824
#define OFF_UZR  15168
#define OFF_CZR  15296
#define OFF_UH   15424
#define OFF_CH   15488
#define SM_WORDS 15552   // 62208 bytes

// one 8-nchunk matvec pass; acc zero-initialized via zero-C first MMA
__device__ __forceinline__ void mv_pass(const uint32_t* __restrict__ Bhi,
                                        const uint32_t* __restrict__ Blo,
                                        const uint32_t* Ah, const uint32_t* Al,
                                        float acc[8][4], int g, int tig, int nchBase){
  #pragma unroll
  for (int n=0;n<8;++n){
    const uint32_t* bh = Bhi + (8*(nchBase+n)+g)*36 + 8*tig;
    const uint32_t* bl = Blo + (8*(nchBase+n)+g)*36 + 8*tig;
    uint4 bh0 = *(const uint4*)bh;
    uint4 bh1 = *(const uint4*)(bh+4);
    uint4 bl0 = *(const uint4*)bl;
    uint4 bl1 = *(const uint4*)(bl+4);
    const uint32_t* bh0p = (const uint32_t*)&bh0;
    const uint32_t* bh1p = (const uint32_t*)&bh1;
    const uint32_t* bl0p = (const uint32_t*)&bl0;
    const uint32_t* bl1p = (const uint32_t*)&bl1;
    mma16816_z(acc[n], Ah[0], Ah[1], Ah[2], Ah[3], bh0p[0], bh1p[0]);
    mma16816 (acc[n], Al[0], Al[1], Al[2], Al[3], bh0p[0], bh1p[0]);
    mma16816 (acc[n], Ah[0], Ah[1], Ah[2], Ah[3], bl0p[0], bl1p[0]);
    #pragma unroll
    for (int kt=1;kt<4;++kt){
      mma16816(acc[n], Ah[4*kt], Ah[4*kt+1], Ah[4*kt+2], Ah[4*kt+3], bh0p[kt], bh1p[kt]);
      mma16816(acc[n], Al[4*kt], Al[4*kt+1], Al[4*kt+2], Al[4*kt+3], bh0p[kt], bh1p[kt]);
      mma16816(acc[n], Ah[4*kt], Ah[4*kt+1], Ah[4*kt+2], Ah[4*kt+3], bl0p[kt], bl1p[kt]);
    }
  }
}

__global__ void __launch_bounds__(128,3) k_hmma(
   const float* __restrict__ Wcz, const float* __restrict__ bcz,
   const float* __restrict__ Wlz, const float* __restrict__ blz,
   const float* __restrict__ Wcr, const float* __restrict__ bcr,
   const float* __restrict__ Wlr, const float* __restrict__ blr,
   const float* __restrict__ Wch, const float* __restrict__ bch,
   const float* __restrict__ Wlh, const float* __restrict__ blh,
   float* __restrict__ out)
{
  extern __shared__ __align__(16) uint32_t sm[];
  float* smf = (float*)sm;

  int tid = threadIdx.x, lane = tid & 31, w = tid >> 5;
  int g = lane >> 2, tig = lane & 3;

  // ---- prologue: weights -> bf16 hi/lo fragment layout ----
  for (int idx = tid; idx < 128*32; idx += 128){
    int n = idx >> 5, p = idx & 31;
    int k0 = 2*p;
    float w0, w1;
    if (n < 64){ w0 = Wlz[(64+k0)*64 + n];  w1 = Wlz[(65+k0)*64 + n]; }
    else       { w0 = Wlr[(64+k0)*64 + n-64]; w1 = Wlr[(65+k0)*64 + n-64]; }
    float h0 = bfhi(w0), h1 = bfhi(w1);
    int q = qmap(p);
    sm[OFF_B1HI + n*36 + q] = bf2pack(h0, h1);
    sm[OFF_B1LO + n*36 + q] = bf2pack(w0-h0, w1-h1);
  }
  for (int idx = tid; idx < 64*32; idx += 128){
    int n = idx >> 5, p = idx & 31;
    int k0 = 2*p;
    float w0 = Wlh[(64+k0)*64 + n], w1 = Wlh[(65+k0)*64 + n];
    float h0 = bfhi(w0), h1 = bfhi(w1);
    int q = qmap(p);
    sm[OFF_B2HI + n*36 + q] = bf2pack(h0, h1);
    sm[OFF_B2LO + n*36 + q] = bf2pack(w0-h0, w1-h1);
  }
  for (int jj = tid; jj < 192; jj += 128){
    if (jj < 128){
      int j = jj & 63;
      const float* W  = (jj<64) ? Wlz : Wlr;
      const float* Wc = (jj<64) ? Wcz : Wcr;
      const float* bc = (jj<64) ? bcz : bcr;
      const float* bl = (jj<64) ? blz : blr;
      float u = 0.f, cc = 0.f;
      for (int k=0;k<64;++k){ float ww = W[k*64+j]; u = fmaf(Wc[k], ww, u); cc = fmaf(bc[k], ww, cc); }
      smf[OFF_UZR + jj] = u; smf[OFF_CZR + jj] = cc + bl[j];
    } else {
      int j = jj - 128;
      float u = 0.f, cc = 0.f;
      for (int k=0;k<64;++k){ float ww = Wlh[k*64+j]; u = fmaf(Wch[k], ww, u); cc = fmaf(bch[k], ww, cc); }
      smf[OFF_UH + j] = u; smf[OFF_CH + j] = cc + blh[j];
    }
  }
  int pbase = blockIdx.x*64;
  for (int idx = tid; idx < 64*20; idx += 128){
    int r = idx/20, t = idx - 20*r;
    int p = pbase + r; int b = p/NN, n = p - b*NN;
    smf[OFF_S + r*21 + t] = g_S[n*BT + b*TT + t];
  }
  __syncthreads();

  // warp-local rows
  int r0 = 16*w + g, r1 = r0 + 8;
  int P0 = pbase + r0, P1 = pbase + r1;
  int b0 = P0/NN, n0 = P0 - b0*NN;
  int b1 = P1/NN, n1 = P1 - b1*NN;
  float* out0 = out + ((size_t)(b0*TT)*NN + n0)*72 + 8 + 2*tig;
  float* out1 = out + ((size_t)(b1*TT)*NN + n1)*72 + 8 + 2*tig;
  const float* S0 = smf + OFF_S + r0*21;
  const float* S1 = smf + OFF_S + r1*21;

  const float2* uzr2 = (const float2*)(smf + OFF_UZR);
  const float2* czr2 = (const float2*)(smf + OFF_CZR);
  const float2* uh22 = (const float2*)(smf + OFF_UH);
  const float2* ch22 = (const float2*)(smf + OFF_CH);

  float h[8][4];
  uint32_t Ah[16], Al[16];

  // ---- t = 0: H = 0, closed form ----
  {
    float s0 = S0[0], s1 = S1[0];
    #pragma unroll
    for (int n=0;n<8;++n){
      float2 uz = uzr2[4*n+tig], cz = czr2[4*n+tig];
      float2 uh = uh22[4*n+tig], ch = ch22[4*n+tig];
      #pragma unroll
      for (int j=0;j<4;++j){
        float s = (j<2) ? s0 : s1;
        float u  = (j&1) ? uz.y : uz.x;
        float c  = (j&1) ? cz.y : cz.x;
        float uu = (j&1) ? uh.y : uh.x;
        float cc = (j&1) ? ch.y : ch.x;
        float z  = sigm(fmaf(s, u, c));
        float ht = tanhap(fmaf(s, uu, cc));
        h[n][j] = (1.f - z)*ht;
      }
      *(float2*)(out0 + 8*n) = make_float2(h[n][0], h[n][1]);
      *(float2*)(out1 + 8*n) = make_float2(h[n][2], h[n][3]);
      int kt = n>>1, half = n&1;
      pack2(h[n][0], h[n][1], Ah[4*kt+2*half],   Al[4*kt+2*half]);
      pack2(h[n][2], h[n][3], Ah[4*kt+2*half+1], Al[4*kt+2*half+1]);
    }
    out0 += (size_t)NN*72;
    out1 += (size_t)NN*72;
  }

  for (int t=1; t<TT; ++t){
    float s0 = S0[t], s1 = S1[t];
    float acc[8][4];

    // ---- pass 1a: z (cols 0..63) ----
    mv_pass(sm + OFF_B1HI, sm + OFF_B1LO, Ah, Al, acc, g, tig, 0);
    float z[8][4];
    #pragma unroll
    for (int n=0;n<8;++n){
      float2 uz = uzr2[4*n+tig], cz = czr2[4*n+tig];
      #pragma unroll
      for (int j=0;j<4;++j){
        float s = (j<2) ? s0 : s1;
        float u = (j&1) ? uz.y : uz.x;
        float c = (j&1) ? cz.y : cz.x;
        z[n][j] = sigm(acc[n][j] + fmaf(s, u, c));
      }
    }

    // ---- pass 1b: r (cols 64..127) -> HR packed straight into A frags ----
    mv_pass(sm + OFF_B1HI, sm + OFF_B1LO, Ah, Al, acc, g, tig, 8);
    #pragma unroll
    for (int n=0;n<8;++n){
      float2 uz = uzr2[32 + 4*n+tig], cz = czr2[32 + 4*n+tig];
      float hr[4];
      #pragma unroll
      for (int j=0;j<4;++j){
        float s = (j<2) ? s0 : s1;
        float u = (j&1) ? uz.y : uz.x;
        float c = (j&1) ? cz.y : cz.x;
        float r = sigm(acc[n][j] + fmaf(s, u, c));
        hr[j] = h[n][j] * r;
      }
      int kt = n>>1, half = n&1;
      pack2(hr[0], hr[1], Ah[4*kt+2*half],   Al[4*kt+2*half]);
      pack2(hr[2], hr[3], Ah[4*kt+2*half+1], Al[4*kt+2*half+1]);
    }

    // ---- pass 2: htil = HR . Uh; blend; out; repack H ----
    mv_pass(sm + OFF_B2HI, sm + OFF_B2LO, Ah, Al, acc, g, tig, 0);
    #pragma unroll
    for (int n=0;n<8;++n){
      float2 uh = uh22[4*n+tig], ch = ch22[4*n+tig];
      #pragma unroll
      for (int j=0;j<4;++j){
        float s = (j<2) ? s0 : s1;
        float u = (j&1) ? uh.y : uh.x;
        float c = (j&1) ? ch.y : ch.x;
        float ht = tanhap(acc[n][j] + fmaf(s, u, c));
        h[n][j] = fmaf(z[n][j], h[n][j] - ht, ht);
      }
      *(float2*)(out0 + 8*n) = make_float2(h[n][0], h[n][1]);
      *(float2*)(out1 + 8*n) = make_float2(h[n][2], h[n][3]);
      int kt = n>>1, half = n&1;
      pack2(h[n][0], h[n][1], Ah[4*kt+2*half],   Al[4*kt+2*half]);
      pack2(h[n][2], h[n][3], Ah[4*kt+2*half+1], Al[4*kt+2*half+1]);
    }
    out0 += (size_t)NN*72;
    out1 += (size_t)NN*72;
  }
}

extern "C" void kernel_launch(void* const* d_in, const int* in_sizes, int n_in,
                              void* d_out, int out_size) {
  const float* obs = (const float*)d_in[0];
  const int* ei32 = (const int*)d_in[1];
  int E = in_sizes[1] / 2;
  if (E > MAXE) E = MAXE;
  float* out = (float*)d_out;

  const int SMB = SM_WORDS*4;   // 62208 B
  cudaFuncSetAttribute(k_hmma, cudaFuncAttributeMaxDynamicSharedMemorySize, SMB);

  int obsBlocks = (BT*NN+255)/256;
  int cntBlocks = (E+255)/256;
  k_pre<<<(NN+255)/256, 256>>>(ei32);
  k_obs_count<<<obsBlocks+cntBlocks, 256>>>(obs, out, ei32, E, obsBlocks);
  k_scan<<<1, 256>>>();
  k_fill<<<cntBlocks, 256>>>(ei32, E);
  k_spmm<<<(NN*5*32+255)/256, 256>>>();
  k_hmma<<<(BB*NN)/64, 128, SMB>>>(
    (const float*)d_in[2], (const float*)d_in[3], (const float*)d_in[4], (const float*)d_in[5],
    (const float*)d_in[6], (const float*)d_in[7], (const float*)d_in[8], (const float*)d_in[9],
    (const float*)d_in[10], (const float*)d_in[11], (const float*)d_in[12], (const float*)d_in[13],
    out);
}